// round 14
// baseline (speedup 1.0000x reference)
#include <cuda_runtime.h>
#include <cuda_bf16.h>
#include <math.h>
#include <stdint.h>

#define Bsz 8
#define Lsz 512
#define IDIM 1024
#define Dm 512
#define Hh 8
#define DH 64
#define NBINS 25
#define PWc 10
#define HALFc 256
#define ISZ 513

#define Mrows (Bsz*Lsz)          // 4096
#define M2 (2*Mrows)             // 8192 combined

typedef __nv_bfloat16 bf16;

// ------------------------- fp32 scratch -------------------------
__device__ float g_xf [(size_t)M2*Dm];
__device__ float g_cmraw[(size_t)NBINS*Lsz*Lsz];   // single-b slice, reused
__device__ float g_cm1[Bsz*Lsz*Lsz];
__device__ float g_cs [Bsz*Lsz*Lsz];
__device__ float g_I  [Bsz*ISZ*ISZ];

// ------------------------- bf16 hi/lo planes -------------------------
__device__ bf16 g_x1ih[Mrows*IDIM], g_x1il[Mrows*IDIM];
__device__ bf16 g_x2ih[Mrows*IDIM], g_x2il[Mrows*IDIM];
__device__ bf16 g_wph[Dm*IDIM],  g_wpl[Dm*IDIM];
__device__ bf16 g_miwh[3*Dm*Dm], g_miwl[3*Dm*Dm];
__device__ bf16 g_mowh[Dm*Dm],   g_mowl[Dm*Dm];
__device__ bf16 g_ciwh[3*Dm*Dm], g_ciwl[3*Dm*Dm];
__device__ bf16 g_cowh[Dm*Dm],   g_cowl[Dm*Dm];
__device__ bf16 g_xh[(size_t)M2*Dm], g_xl[(size_t)M2*Dm];
__device__ bf16 g_th[(size_t)M2*Dm], g_tl[(size_t)M2*Dm];
__device__ bf16 g_qkh[(size_t)M2*2*Dm], g_qkl[(size_t)M2*2*Dm];   // Q | K combined
__device__ bf16 g_vth[(size_t)Dm*M2], g_vtl[(size_t)Dm*M2];
__device__ bf16 g_oh[(size_t)M2*Dm], g_ol[(size_t)M2*Dm];
__device__ bf16 g_wbth[NBINS*HALFc*Dm], g_wbtl[NBINS*HALFc*Dm];
__device__ bf16 g_hh[(size_t)2*Bsz*NBINS*Lsz*HALFc];
__device__ bf16 g_hl[(size_t)2*Bsz*NBINS*Lsz*HALFc];

// ------------------------- helpers -------------------------
__device__ __forceinline__ uint32_t smem_u32(const void* p){
    uint32_t a;
    asm("{ .reg .u64 t; cvta.to.shared.u64 t, %1; cvt.u32.u64 %0, t; }" : "=r"(a) : "l"(p));
    return a;
}
__device__ __forceinline__ void cp16(uint32_t dst, const void* src){
    asm volatile("cp.async.cg.shared.global [%0], [%1], 16;" :: "r"(dst), "l"(src));
}
#define CP_COMMIT() asm volatile("cp.async.commit_group;" ::: "memory")
#define CP_WAIT(n)  asm volatile("cp.async.wait_group %0;" :: "n"(n) : "memory")

__device__ __forceinline__ uint4 ldm4(uint32_t addr){
    uint4 r;
    asm volatile("ldmatrix.sync.aligned.m8n8.x4.shared.b16 {%0,%1,%2,%3}, [%4];"
        : "=r"(r.x), "=r"(r.y), "=r"(r.z), "=r"(r.w) : "r"(addr));
    return r;
}
__device__ __forceinline__ void mma_bf16(float c[4], uint4 a, uint32_t b0, uint32_t b1){
    asm volatile("mma.sync.aligned.m16n8k16.row.col.f32.bf16.bf16.f32 "
        "{%0,%1,%2,%3}, {%4,%5,%6,%7}, {%8,%9}, {%0,%1,%2,%3};"
        : "+f"(c[0]), "+f"(c[1]), "+f"(c[2]), "+f"(c[3])
        : "r"(a.x), "r"(a.y), "r"(a.z), "r"(a.w), "r"(b0), "r"(b1));
}

// fp32 -> bf16 hi (truncate) / lo (rn of remainder)
__device__ __forceinline__ void cvt_hilo(float4 v, uint2& hi, uint2& lo){
    uint32_t ux = __float_as_uint(v.x), uy = __float_as_uint(v.y),
             uz = __float_as_uint(v.z), uw = __float_as_uint(v.w);
    float hx = __uint_as_float(ux & 0xffff0000u);
    float hy = __uint_as_float(uy & 0xffff0000u);
    float hz = __uint_as_float(uz & 0xffff0000u);
    float hw = __uint_as_float(uw & 0xffff0000u);
    asm("prmt.b32 %0, %1, %2, 0x7632;" : "=r"(hi.x) : "r"(ux), "r"(uy));
    asm("prmt.b32 %0, %1, %2, 0x7632;" : "=r"(hi.y) : "r"(uz), "r"(uw));
    float lx = v.x - hx, ly = v.y - hy, lz = v.z - hz, lw = v.w - hw;
    asm("cvt.rn.bf16x2.f32 %0, %1, %2;" : "=r"(lo.x) : "f"(ly), "f"(lx));
    asm("cvt.rn.bf16x2.f32 %0, %1, %2;" : "=r"(lo.y) : "f"(lw), "f"(lz));
}
__device__ __forceinline__ void cvt_hilo2(float v0, float v1, uint32_t& h, uint32_t& l){
    uint32_t u0 = __float_as_uint(v0), u1 = __float_as_uint(v1);
    asm("prmt.b32 %0, %1, %2, 0x7632;" : "=r"(h) : "r"(u0), "r"(u1));
    float h0 = __uint_as_float(u0 & 0xffff0000u);
    float h1 = __uint_as_float(u1 & 0xffff0000u);
    asm("cvt.rn.bf16x2.f32 %0, %1, %2;" : "=r"(l) : "f"(v1-h1), "f"(v0-h0));
}
__device__ __forceinline__ void split1(float x, bf16* h, bf16* l){
    uint32_t ux = __float_as_uint(x);
    __nv_bfloat16_raw r; r.x = (unsigned short)(ux >> 16);
    *h = r;
    float hf = __uint_as_float(ux & 0xffff0000u);
    *l = __float2bfloat16(x - hf);
}

// ------------------------- mma.sync GEMM -------------------------
template<int BN>
__global__ void __launch_bounds__(256, 2)
gemm_mma(const bf16* __restrict__ Ah, const bf16* __restrict__ Al,
         const bf16* __restrict__ Bh, const bf16* __restrict__ Bl,
         float* __restrict__ C, bf16* __restrict__ Ch, bf16* __restrict__ Cl,
         int K, int lda, int ldb, int ldc,
         long long sA1, long long sA2, long long sB1, long long sB2,
         long long sC1, long long sC2, int batch2,
         const float* __restrict__ bias, int biasMode, float alpha, int act,
         const float* __restrict__ Cres, int outMode)
{
    constexpr int BM = 128, BK = 32;
    constexpr int ROWB = BK*2 + 16;
    constexpr int APL = BM * ROWB;
    constexpr int BPL = BN * ROWB;
    constexpr int STAGE = 2*APL + 2*BPL;
    constexpr int WN = BN / 2;
    constexpr int NB = WN / 8;
    constexpr int KCH = BK / 8;
    constexpr int NCHUNK = (2*BM + 2*BN) * KCH;

    extern __shared__ __align__(128) char smem[];
    const uint32_t sb = smem_u32(smem);

    const int z = blockIdx.z, z1 = z / batch2, z2 = z % batch2;
    const long long aoff = z1*sA1 + z2*sA2;
    const long long boff = z1*sB1 + z2*sB2;
    const long long coff = z1*sC1 + z2*sC2;
    Ah += aoff; Al += aoff;
    Bh += boff; Bl += boff;

    const int m0 = blockIdx.y * BM;
    const int n0 = blockIdx.x * BN;
    const int tid = threadIdx.x;
    const int wid = tid >> 5, lane = tid & 31;
    const int wm = wid >> 1, wn = wid & 1;
    const int mbase = wm * 32;
    const int nbase = wn * WN;

    float acc[2][NB][4];
    #pragma unroll
    for (int i = 0; i < 2; i++)
        #pragma unroll
        for (int j = 0; j < NB; j++)
            #pragma unroll
            for (int u = 0; u < 4; u++) acc[i][j][u] = 0.f;

    const int NC = K / BK;

    auto stage_copy = [&](int c, int s){
        const uint32_t st = sb + (uint32_t)s * STAGE;
        #pragma unroll
        for (int i = 0; i < NCHUNK/256; i++) {
            int idx = tid + i*256;
            const bf16* src; uint32_t dst;
            if (idx < 2*BM*KCH) {
                int p = idx / (BM*KCH); int rem = idx - p*BM*KCH;
                int r = rem >> 2, cc = rem & 3;
                src = (p ? Al : Ah) + (long long)(m0+r)*lda + c*BK + cc*8;
                dst = st + p*APL + r*ROWB + cc*16;
            } else {
                int j = idx - 2*BM*KCH;
                int p = j / (BN*KCH); int rem = j - p*BN*KCH;
                int r = rem >> 2, cc = rem & 3;
                src = (p ? Bl : Bh) + (long long)(n0+r)*ldb + c*BK + cc*8;
                dst = st + 2*APL + p*BPL + r*ROWB + cc*16;
            }
            cp16(dst, src);
        }
    };

    auto compute = [&](int s){
        const uint32_t st = sb + (uint32_t)s * STAGE;
        const uint32_t ab = st;
        const uint32_t bb = st + 2*APL;
        const int arow = mbase + (lane & 15);
        const int akoff = ((lane >> 4) & 1) * 16;
        const int brow0 = nbase + (lane & 7) + ((lane >> 4) & 1) * 8;
        const int bkoff = ((lane >> 3) & 1) * 16;
        #pragma unroll
        for (int ks = 0; ks < BK/16; ks++) {
            const int kb = ks * 32;
            uint4 a[2][2];
            #pragma unroll
            for (int p = 0; p < 2; p++)
                #pragma unroll
                for (int mb = 0; mb < 2; mb++)
                    a[p][mb] = ldm4(ab + p*APL + (arow + mb*16)*ROWB + kb + akoff);
            #pragma unroll
            for (int nb2 = 0; nb2 < NB/2; nb2++) {
                uint4 b0 = ldm4(bb + (brow0 + nb2*16)*ROWB + kb + bkoff);
                uint4 b1 = ldm4(bb + BPL + (brow0 + nb2*16)*ROWB + kb + bkoff);
                #pragma unroll
                for (int mb = 0; mb < 2; mb++) {
                    float* c0 = acc[mb][2*nb2];
                    float* c1 = acc[mb][2*nb2+1];
                    mma_bf16(c0, a[0][mb], b0.x, b0.y);
                    mma_bf16(c1, a[0][mb], b0.z, b0.w);
                    mma_bf16(c0, a[0][mb], b1.x, b1.y);
                    mma_bf16(c1, a[0][mb], b1.z, b1.w);
                    mma_bf16(c0, a[1][mb], b0.x, b0.y);
                    mma_bf16(c1, a[1][mb], b0.z, b0.w);
                }
            }
        }
    };

    stage_copy(0, 0);
    CP_COMMIT();
    for (int c = 0; c < NC; c++) {
        CP_WAIT(0);
        __syncthreads();
        if (c + 1 < NC) { stage_copy(c + 1, (c + 1) & 1); CP_COMMIT(); }
        compute(c & 1);
    }

    const int g = lane >> 2, t = lane & 3;
    #pragma unroll
    for (int mb = 0; mb < 2; mb++) {
        #pragma unroll
        for (int half = 0; half < 2; half++) {
            const int row = m0 + mbase + mb*16 + g + half*8;
            const long long rowo = coff + (long long)row * ldc;
            float brow = (biasMode == 2) ? bias[row] : 0.f;
            #pragma unroll
            for (int nb = 0; nb < NB; nb++) {
                const int col = n0 + nbase + nb*8 + 2*t;
                float v0 = acc[mb][nb][half*2+0] * alpha;
                float v1 = acc[mb][nb][half*2+1] * alpha;
                if (biasMode == 1) {
                    float2 bb = *reinterpret_cast<const float2*>(&bias[col]);
                    v0 += bb.x; v1 += bb.y;
                } else if (biasMode == 2) {
                    v0 += brow; v1 += brow;
                }
                if (Cres) {
                    float2 rr = *reinterpret_cast<const float2*>(&Cres[rowo + col]);
                    v0 += rr.x; v1 += rr.y;
                }
                if (act) { v0 = tanhf(v0); v1 = tanhf(v1); }
                if (outMode & 1)
                    *reinterpret_cast<float2*>(&C[rowo + col]) = make_float2(v0, v1);
                if (outMode & 2) {
                    uint32_t h, l;
                    cvt_hilo2(v0, v1, h, l);
                    *reinterpret_cast<uint32_t*>(&Ch[rowo + col]) = h;
                    *reinterpret_cast<uint32_t*>(&Cl[rowo + col]) = l;
                }
            }
        }
    }
}

// ------------------------- fused attention -------------------------
// Q and K live in the combined qk buffer (row stride 2*Dm; K at col offset Dm).
__global__ void __launch_bounds__(256, 1)
fused_attn(const bf16* __restrict__ QKh, const bf16* __restrict__ QKl,
           const bf16* __restrict__ Vth, const bf16* __restrict__ Vtl,
           bf16* __restrict__ Oh, bf16* __restrict__ Ol)
{
    constexpr int LDQ = 2*Dm;                // 1024
    constexpr int QROWB = 144;
    constexpr int KROWB = 144;
    constexpr int VROWB = 272;
    constexpr int QPL = 128 * QROWB;
    constexpr int KPL = 128 * KROWB;
    constexpr int VPL = 64 * VROWB;

    extern __shared__ __align__(128) char smem[];
    const uint32_t sbm = smem_u32(smem);
    const uint32_t qb = sbm;
    const uint32_t kbb = qb + 2*QPL;
    const uint32_t vb = kbb + 2*KPL;
    float* maxred = reinterpret_cast<float*>(smem + 2*QPL + 2*KPL + 2*VPL);
    float* sumred = maxred + 256;
    float* oex    = sumred + 256;

    const int tid = threadIdx.x;
    const int wid = tid >> 5, lane = tid & 31;
    const int wm = wid >> 1, wn = wid & 1;
    const int g = lane >> 2, t = lane & 3;

    const int sbatch = blockIdx.y >> 3;
    const int h = blockIdx.y & 7;
    const long long tb = (long long)sbatch * Lsz;
    const int q0 = blockIdx.x * 128;

    #pragma unroll
    for (int i = 0; i < 8; i++) {
        int idx = tid + i*256;
        int p = idx >> 10, rem = idx & 1023;
        int r = rem >> 3, cc = rem & 7;
        const bf16* src = (p ? QKl : QKh) + (tb + q0 + r)*LDQ + h*DH + cc*8;
        cp16(qb + p*QPL + r*QROWB + cc*16, src);
    }

    auto stage_kv = [&](int kt){
        #pragma unroll
        for (int i = 0; i < 8; i++) {
            int idx = tid + i*256;
            int p = idx >> 10, rem = idx & 1023;
            int r = rem >> 3, cc = rem & 7;
            const bf16* src = (p ? QKl : QKh) + (tb + kt*128 + r)*LDQ + Dm + h*DH + cc*8;
            cp16(kbb + p*KPL + r*KROWB + cc*16, src);
        }
        #pragma unroll
        for (int i = 0; i < 8; i++) {
            int idx = tid + i*256;
            int p = idx >> 10, rem = idx & 1023;
            int r = rem >> 4, cc = rem & 15;
            const bf16* src = (p ? Vtl : Vth) + (long long)(h*DH + r)*M2 + tb + kt*128 + cc*8;
            cp16(vb + p*VPL + r*VROWB + cc*16, src);
        }
    };

    float oacc[2][8][4];
    float sacc[2][8][4];
    float mrow[2][2], lrow[2][2];
    #pragma unroll
    for (int mb = 0; mb < 2; mb++) {
        #pragma unroll
        for (int nb = 0; nb < 8; nb++)
            #pragma unroll
            for (int u = 0; u < 4; u++) oacc[mb][nb][u] = 0.f;
        mrow[mb][0] = -1e30f; mrow[mb][1] = -1e30f;
        lrow[mb][0] = 0.f;    lrow[mb][1] = 0.f;
    }

    stage_kv(0);
    CP_COMMIT(); CP_WAIT(0);
    __syncthreads();

    const int arow  = wm*32 + (lane & 15);
    const int akoff = ((lane >> 4) & 1) * 16;
    const int brow0 = wn*64 + (lane & 7) + ((lane >> 4) & 1) * 8;
    const int bkoff = ((lane >> 3) & 1) * 16;
    const int dbrow0 = (lane & 7) + ((lane >> 4) & 1) * 8;

    for (int kt = 0; kt < 4; kt++) {
        #pragma unroll
        for (int mb = 0; mb < 2; mb++)
            #pragma unroll
            for (int nb = 0; nb < 8; nb++)
                #pragma unroll
                for (int u = 0; u < 4; u++) sacc[mb][nb][u] = 0.f;
        #pragma unroll
        for (int ks = 0; ks < 4; ks++) {
            const int kb2 = ks * 32;
            uint4 a[2][2];
            #pragma unroll
            for (int p = 0; p < 2; p++)
                #pragma unroll
                for (int mb = 0; mb < 2; mb++)
                    a[p][mb] = ldm4(qb + p*QPL + (arow + mb*16)*QROWB + kb2 + akoff);
            #pragma unroll
            for (int nb2 = 0; nb2 < 4; nb2++) {
                uint4 b0 = ldm4(kbb + (brow0 + nb2*16)*KROWB + kb2 + bkoff);
                uint4 b1 = ldm4(kbb + KPL + (brow0 + nb2*16)*KROWB + kb2 + bkoff);
                #pragma unroll
                for (int mb = 0; mb < 2; mb++) {
                    float* c0 = sacc[mb][2*nb2];
                    float* c1 = sacc[mb][2*nb2+1];
                    mma_bf16(c0, a[0][mb], b0.x, b0.y);
                    mma_bf16(c1, a[0][mb], b0.z, b0.w);
                    mma_bf16(c0, a[0][mb], b1.x, b1.y);
                    mma_bf16(c1, a[0][mb], b1.z, b1.w);
                    mma_bf16(c0, a[1][mb], b0.x, b0.y);
                    mma_bf16(c1, a[1][mb], b0.z, b0.w);
                }
            }
        }
        #pragma unroll
        for (int mb = 0; mb < 2; mb++)
            #pragma unroll
            for (int nb = 0; nb < 8; nb++)
                #pragma unroll
                for (int u = 0; u < 4; u++) sacc[mb][nb][u] *= 0.125f;
        #pragma unroll
        for (int mb = 0; mb < 2; mb++)
            #pragma unroll
            for (int half = 0; half < 2; half++) {
                float mx = -1e30f;
                #pragma unroll
                for (int nb = 0; nb < 8; nb++) {
                    mx = fmaxf(mx, sacc[mb][nb][half*2]);
                    mx = fmaxf(mx, sacc[mb][nb][half*2+1]);
                }
                mx = fmaxf(mx, __shfl_xor_sync(0xffffffffu, mx, 1));
                mx = fmaxf(mx, __shfl_xor_sync(0xffffffffu, mx, 2));
                if (t == 0) maxred[wn*128 + wm*32 + mb*16 + g + half*8] = mx;
            }
        __syncthreads();
        #pragma unroll
        for (int mb = 0; mb < 2; mb++)
            #pragma unroll
            for (int half = 0; half < 2; half++) {
                const int r = wm*32 + mb*16 + g + half*8;
                float mt = fmaxf(maxred[r], maxred[128 + r]);
                float mnew = fmaxf(mrow[mb][half], mt);
                float corr = expf(mrow[mb][half] - mnew);
                mrow[mb][half] = mnew;
                lrow[mb][half] *= corr;
                float sum = 0.f;
                #pragma unroll
                for (int nb = 0; nb < 8; nb++) {
                    float p0 = expf(sacc[mb][nb][half*2]   - mnew);
                    float p1 = expf(sacc[mb][nb][half*2+1] - mnew);
                    sacc[mb][nb][half*2]   = p0;
                    sacc[mb][nb][half*2+1] = p1;
                    sum += p0 + p1;
                    oacc[mb][nb][half*2]   *= corr;
                    oacc[mb][nb][half*2+1] *= corr;
                }
                sum += __shfl_xor_sync(0xffffffffu, sum, 1);
                sum += __shfl_xor_sync(0xffffffffu, sum, 2);
                if (t == 0) sumred[wn*128 + r] = sum;
            }
        __syncthreads();
        #pragma unroll
        for (int mb = 0; mb < 2; mb++)
            #pragma unroll
            for (int half = 0; half < 2; half++) {
                const int r = wm*32 + mb*16 + g + half*8;
                lrow[mb][half] += sumred[r] + sumred[128 + r];
            }
        #pragma unroll
        for (int ksp = 0; ksp < 4; ksp++) {
            uint4 pah[2], pal[2];
            #pragma unroll
            for (int mb = 0; mb < 2; mb++) {
                float* b0p = sacc[mb][2*ksp];
                float* b1p = sacc[mb][2*ksp+1];
                cvt_hilo2(b0p[0], b0p[1], pah[mb].x, pal[mb].x);
                cvt_hilo2(b0p[2], b0p[3], pah[mb].y, pal[mb].y);
                cvt_hilo2(b1p[0], b1p[1], pah[mb].z, pal[mb].z);
                cvt_hilo2(b1p[2], b1p[3], pah[mb].w, pal[mb].w);
            }
            const int vcol = (wn*64 + ksp*16)*2 + bkoff;
            #pragma unroll
            for (int nb2 = 0; nb2 < 4; nb2++) {
                uint4 bh = ldm4(vb + (dbrow0 + nb2*16)*VROWB + vcol);
                uint4 bl = ldm4(vb + VPL + (dbrow0 + nb2*16)*VROWB + vcol);
                #pragma unroll
                for (int mb = 0; mb < 2; mb++) {
                    float* c0 = oacc[mb][2*nb2];
                    float* c1 = oacc[mb][2*nb2+1];
                    mma_bf16(c0, pah[mb], bh.x, bh.y);
                    mma_bf16(c1, pah[mb], bh.z, bh.w);
                    mma_bf16(c0, pah[mb], bl.x, bl.y);
                    mma_bf16(c1, pah[mb], bl.z, bl.w);
                    mma_bf16(c0, pal[mb], bh.x, bh.y);
                    mma_bf16(c1, pal[mb], bh.z, bh.w);
                }
            }
        }
        __syncthreads();
        if (kt < 3) {
            stage_kv(kt + 1);
            CP_COMMIT(); CP_WAIT(0);
            __syncthreads();
        }
    }

    if (wn == 1) {
        #pragma unroll
        for (int mb = 0; mb < 2; mb++)
            #pragma unroll
            for (int half = 0; half < 2; half++) {
                const int r = wm*32 + mb*16 + g + half*8;
                #pragma unroll
                for (int nb = 0; nb < 8; nb++) {
                    oex[r*64 + nb*8 + 2*t]     = oacc[mb][nb][half*2];
                    oex[r*64 + nb*8 + 2*t + 1] = oacc[mb][nb][half*2+1];
                }
            }
    }
    __syncthreads();
    if (wn == 0) {
        #pragma unroll
        for (int mb = 0; mb < 2; mb++)
            #pragma unroll
            for (int half = 0; half < 2; half++) {
                const int r = wm*32 + mb*16 + g + half*8;
                const float inv = 1.f / lrow[mb][half];
                const long long rowo = (tb + q0 + r)*Dm + h*DH;
                #pragma unroll
                for (int nb = 0; nb < 8; nb++) {
                    const int col = nb*8 + 2*t;
                    float v0 = (oacc[mb][nb][half*2]   + oex[r*64 + col])     * inv;
                    float v1 = (oacc[mb][nb][half*2+1] + oex[r*64 + col + 1]) * inv;
                    uint32_t hh, ll;
                    cvt_hilo2(v0, v1, hh, ll);
                    *reinterpret_cast<uint32_t*>(&Oh[rowo + col]) = hh;
                    *reinterpret_cast<uint32_t*>(&Ol[rowo + col]) = ll;
                }
            }
    }
}

// ------------------------- converts -------------------------
__global__ void split_k(const float* __restrict__ in, bf16* __restrict__ oh,
                        bf16* __restrict__ ol, int n4)
{
    int i = blockIdx.x * blockDim.x + threadIdx.x;
    if (i >= n4) return;
    float4 v = reinterpret_cast<const float4*>(in)[i];
    uint2 h, l; cvt_hilo(v, h, l);
    reinterpret_cast<uint2*>(oh)[i] = h;
    reinterpret_cast<uint2*>(ol)[i] = l;
}
__global__ void tanh_split_k(const float* __restrict__ in, bf16* __restrict__ oh,
                             bf16* __restrict__ ol, int n4)
{
    int i = blockIdx.x * blockDim.x + threadIdx.x;
    if (i >= n4) return;
    float4 v = reinterpret_cast<const float4*>(in)[i];
    v.x = tanhf(v.x); v.y = tanhf(v.y); v.z = tanhf(v.z); v.w = tanhf(v.w);
    uint2 h, l; cvt_hilo(v, h, l);
    reinterpret_cast<uint2*>(oh)[i] = h;
    reinterpret_cast<uint2*>(ol)[i] = l;
}
__global__ void transpose_split_k(const float* __restrict__ in,
                                  bf16* __restrict__ oh, bf16* __restrict__ ol)
{
    __shared__ float tile[32][33];
    int n = blockIdx.z;
    int k0 = blockIdx.x * 32, d0 = blockIdx.y * 32;
    in += (size_t)n * Dm * HALFc;
    oh += (size_t)n * HALFc * Dm;
    ol += (size_t)n * HALFc * Dm;
    int tx = threadIdx.x, ty = threadIdx.y;
    #pragma unroll
    for (int i = ty; i < 32; i += 8)
        tile[i][tx] = in[(d0 + i) * HALFc + k0 + tx];
    __syncthreads();
    #pragma unroll
    for (int i = ty; i < 32; i += 8) {
        bf16 h, l; split1(tile[tx][i], &h, &l);
        oh[(k0 + i) * Dm + d0 + tx] = h;
        ol[(k0 + i) * Dm + d0 + tx] = l;
    }
}

// ------------------------- bin smoothing (single b slice) -------------------------
__global__ void __launch_bounds__(256)
smooth_b(const float* __restrict__ raw, const float* __restrict__ sm,
         const float* __restrict__ agg, float* __restrict__ cm_out,
         float* __restrict__ cm1)
{
    const int PS = Lsz * Lsz / 4;
    int idx = blockIdx.x * blockDim.x + threadIdx.x;
    if (idx >= PS) return;

    const float4* base = reinterpret_cast<const float4*>(raw) + idx;
    float4 rv[NBINS];
    #pragma unroll
    for (int n = 0; n < NBINS; n++) rv[n] = base[(size_t)n * PS];

    float sw[5];
    #pragma unroll
    for (int k = 0; k < 5; k++) sw[k] = sm[k];

    float4* outb = reinterpret_cast<float4*>(cm_out) + idx;
    float4 acc = make_float4(0.f, 0.f, 0.f, 0.f);
    #pragma unroll
    for (int n = 0; n < NBINS; n++) {
        float4 v = make_float4(0.f, 0.f, 0.f, 0.f);
        #pragma unroll
        for (int k = 0; k < 5; k++) {
            int m = n + k - 2;
            if (m >= 0 && m < NBINS) {
                v.x += sw[k] * rv[m].x;
                v.y += sw[k] * rv[m].y;
                v.z += sw[k] * rv[m].z;
                v.w += sw[k] * rv[m].w;
            }
        }
        outb[(size_t)n * PS] = v;
        float a = agg[n];
        acc.x += a * v.x; acc.y += a * v.y;
        acc.z += a * v.z; acc.w += a * v.w;
    }
    float4 o = make_float4(tanhf(acc.x), tanhf(acc.y), tanhf(acc.z), tanhf(acc.w));
    reinterpret_cast<float4*>(cm1)[idx] = o;
}

// ------------------------- integral image + head -------------------------
__global__ void colsum_k(const float* __restrict__ cm1, float* __restrict__ cs)
{
    int t = blockIdx.x * blockDim.x + threadIdx.x;
    if (t >= Bsz * Lsz) return;
    int b = t / Lsz, j = t % Lsz;
    const float* src = cm1 + (long long)b * Lsz * Lsz + j;
    float* dst       = cs  + (long long)b * Lsz * Lsz + j;
    float acc = 0.f;
    for (int i = 0; i < Lsz; i++) {
        acc += src[(long long)i * Lsz];
        dst[(long long)i * Lsz] = acc;
    }
}
__global__ void rowsum_k(const float* __restrict__ cs, float* __restrict__ I)
{
    int t = blockIdx.x * blockDim.x + threadIdx.x;
    if (t >= Bsz * Lsz) return;
    int b = t / Lsz, i = t % Lsz;
    const float* src = cs + (long long)b * Lsz * Lsz + (long long)i * Lsz;
    float* row = I + (long long)b * ISZ * ISZ + (long long)(i + 1) * ISZ;
    float acc = 0.f;
    row[0] = 0.f;
    for (int j = 0; j < Lsz; j++) { acc += src[j]; row[j + 1] = acc; }
    if (i == 0) {
        float* r0 = I + (long long)b * ISZ * ISZ;
        for (int c = 0; c < ISZ; c++) r0[c] = 0.f;
    }
}
__global__ void finalize_k(const float* __restrict__ I, const float* __restrict__ Lmat,
                           const float* __restrict__ biasp, float* __restrict__ pp)
{
    int b = blockIdx.x;
    __shared__ float terms[128];
    int t = threadIdx.x;
    float val = 0.f;
    if (t < PWc * PWc) {
        int p = t / PWc, q = t % PWc;
        const float* Ib = I + (long long)b * ISZ * ISZ;
        const int Hp = Lsz - PWc + 1;
        float w = Ib[(Hp + p) * ISZ + (Hp + q)] - Ib[(Hp + p) * ISZ + q]
                - Ib[p * ISZ + (Hp + q)]       + Ib[p * ISZ + q];
        val = tanhf(w) * Lmat[t];
    }
    terms[t] = val;
    __syncthreads();
    if (t == 0) {
        float s = 0.f;
        for (int i = 0; i < PWc * PWc; i++) s += terms[i];
        pp[b] = 1.0f / (1.0f + expf(-(s + biasp[0])));
    }
}

// ------------------------- host-side -------------------------
static int SMEM_TOTAL_BYTES(int BN) { return 2 * (2*128 + 2*BN) * (32*2 + 16); }
static int FA_SMEM() { return 2*128*144 + 2*128*144 + 2*64*272 + (256 + 256 + 128*64)*4; }

static void gemm(int BN, const bf16* Ah, const bf16* Al, const bf16* Bh, const bf16* Bl,
                 float* C, bf16* Ch, bf16* Cl,
                 int M, int N, int K, int lda, int ldb, int ldc,
                 long long sA1, long long sA2, long long sB1, long long sB2,
                 long long sC1, long long sC2, int batch1, int batch2,
                 const float* bias, int biasMode, float alpha, int act,
                 const float* Cres, int outMode)
{
    dim3 grid(N / BN, M / 128, batch1 * batch2);
    if (BN == 128)
        gemm_mma<128><<<grid, 256, SMEM_TOTAL_BYTES(128)>>>(Ah, Al, Bh, Bl, C, Ch, Cl,
            K, lda, ldb, ldc, sA1, sA2, sB1, sB2, sC1, sC2, batch2,
            bias, biasMode, alpha, act, Cres, outMode);
    else
        gemm_mma<64><<<grid, 256, SMEM_TOTAL_BYTES(64)>>>(Ah, Al, Bh, Bl, C, Ch, Cl,
            K, lda, ldb, ldc, sA1, sA2, sB1, sB2, sC1, sC2, batch2,
            bias, biasMode, alpha, act, Cres, outMode);
}

struct Ptrs {
    float *xf, *cmraw, *cm1, *cs, *I;
    bf16 *x1ih,*x1il,*x2ih,*x2il,*wph,*wpl,*miwh,*miwl,*mowh,*mowl,*ciwh,*ciwl,*cowh,*cowl;
    bf16 *xh,*xl,*th,*tl,*qkh,*qkl,*vth,*vtl,*oh,*ol;
    bf16 *wbth,*wbtl,*hh,*hl;
};

static void run_mha(const Ptrs& P,
                    const bf16* qsh, const bf16* qsl,
                    const bf16* kvh, const bf16* kvl,
                    const bf16* iwh, const bf16* iwl, const float* in_b,
                    const bf16* owh, const bf16* owl, const float* out_b,
                    float* target, bool swapKV)
{
    const long long MD = (long long)Mrows * Dm;
    if (!swapKV) {
        // fused Q+K projection: N=1024, weights rows 0..1023 contiguous
        gemm(128, qsh, qsl, iwh, iwl, nullptr, P.qkh, P.qkl,
             M2, 2*Dm, Dm, Dm, Dm, 2*Dm, 0,0,0,0,0,0, 1,1, in_b, 1, 1.f, 0, nullptr, 2);
        gemm(128, iwh + 2*Dm*Dm, iwl + 2*Dm*Dm, kvh, kvl, nullptr, P.vth, P.vtl,
             Dm, M2, Dm, Dm, Dm, M2, 0,0,0,0,0,0, 1,1, in_b + 2*Dm, 2, 1.f, 0, nullptr, 2);
    } else {
        // Q into qk cols [0,512)
        gemm(128, qsh, qsl, iwh, iwl, nullptr, P.qkh, P.qkl,
             M2, Dm, Dm, Dm, Dm, 2*Dm, 0,0,0,0,0,0, 1,1, in_b, 1, 1.f, 0, nullptr, 2);
        // swapped K into qk cols [512,1024): batch z1 A = kv + z1*MD, C rows swapped
        gemm(128, kvh, kvl, iwh + Dm*Dm, iwl + Dm*Dm, nullptr,
             P.qkh + Dm + (long long)Mrows*2*Dm, P.qkl + Dm + (long long)Mrows*2*Dm,
             Mrows, Dm, Dm, Dm, Dm, 2*Dm,
             MD, 0, 0, 0, -(long long)Mrows*2*Dm, 0, 2, 1, in_b + Dm, 1, 1.f, 0, nullptr, 2);
        gemm(128, iwh + 2*Dm*Dm, iwl + 2*Dm*Dm, kvh, kvl, nullptr, P.vth + Mrows, P.vtl + Mrows,
             Dm, Mrows, Dm, Dm, Dm, M2,
             0, 0, MD, 0, -(long long)Mrows, 0, 2, 1, in_b + 2*Dm, 2, 1.f, 0, nullptr, 2);
    }
    fused_attn<<<dim3(4, 2*Bsz*Hh), 256, FA_SMEM()>>>(
        P.qkh, P.qkl, P.vth, P.vtl, P.oh, P.ol);
    gemm(128, P.oh, P.ol, owh, owl, target, nullptr, nullptr,
         M2, Dm, Dm, Dm, Dm, Dm, 0,0,0,0,0,0, 1,1, out_b, 1, 1.f, 0, target, 1);
}

extern "C" void kernel_launch(void* const* d_in, const int* in_sizes, int n_in,
                              void* d_out, int out_size)
{
    const float* x1i     = (const float*)d_in[0];
    const float* x2i     = (const float*)d_in[1];
    const float* proj_w  = (const float*)d_in[2];
    const float* proj_b  = (const float*)d_in[3];
    const float* mha_in_w  = (const float*)d_in[4];
    const float* mha_in_b  = (const float*)d_in[5];
    const float* mha_out_w = (const float*)d_in[6];
    const float* mha_out_b = (const float*)d_in[7];
    const float* ca_in_w   = (const float*)d_in[8];
    const float* ca_in_b   = (const float*)d_in[9];
    const float* ca_out_w  = (const float*)d_in[10];
    const float* ca_out_b  = (const float*)d_in[11];
    const float* Wbins   = (const float*)d_in[12];
    const float* agg     = (const float*)d_in[13];
    const float* Lmat    = (const float*)d_in[14];
    const float* biasp   = (const float*)d_in[15];
    const float* smooth  = (const float*)d_in[16];

    cudaFuncSetAttribute(gemm_mma<128>, cudaFuncAttributeMaxDynamicSharedMemorySize,
                         SMEM_TOTAL_BYTES(128));
    cudaFuncSetAttribute(gemm_mma<64>,  cudaFuncAttributeMaxDynamicSharedMemorySize,
                         SMEM_TOTAL_BYTES(64));
    cudaFuncSetAttribute(fused_attn, cudaFuncAttributeMaxDynamicSharedMemorySize,
                         FA_SMEM());

    Ptrs P;
    cudaGetSymbolAddress((void**)&P.xf, g_xf);
    cudaGetSymbolAddress((void**)&P.cmraw, g_cmraw);
    cudaGetSymbolAddress((void**)&P.cm1, g_cm1);   cudaGetSymbolAddress((void**)&P.cs, g_cs);
    cudaGetSymbolAddress((void**)&P.I, g_I);
    cudaGetSymbolAddress((void**)&P.x1ih, g_x1ih); cudaGetSymbolAddress((void**)&P.x1il, g_x1il);
    cudaGetSymbolAddress((void**)&P.x2ih, g_x2ih); cudaGetSymbolAddress((void**)&P.x2il, g_x2il);
    cudaGetSymbolAddress((void**)&P.wph, g_wph);   cudaGetSymbolAddress((void**)&P.wpl, g_wpl);
    cudaGetSymbolAddress((void**)&P.miwh, g_miwh); cudaGetSymbolAddress((void**)&P.miwl, g_miwl);
    cudaGetSymbolAddress((void**)&P.mowh, g_mowh); cudaGetSymbolAddress((void**)&P.mowl, g_mowl);
    cudaGetSymbolAddress((void**)&P.ciwh, g_ciwh); cudaGetSymbolAddress((void**)&P.ciwl, g_ciwl);
    cudaGetSymbolAddress((void**)&P.cowh, g_cowh); cudaGetSymbolAddress((void**)&P.cowl, g_cowl);
    cudaGetSymbolAddress((void**)&P.xh, g_xh);     cudaGetSymbolAddress((void**)&P.xl, g_xl);
    cudaGetSymbolAddress((void**)&P.th, g_th);     cudaGetSymbolAddress((void**)&P.tl, g_tl);
    cudaGetSymbolAddress((void**)&P.qkh, g_qkh);   cudaGetSymbolAddress((void**)&P.qkl, g_qkl);
    cudaGetSymbolAddress((void**)&P.vth, g_vth);   cudaGetSymbolAddress((void**)&P.vtl, g_vtl);
    cudaGetSymbolAddress((void**)&P.oh, g_oh);     cudaGetSymbolAddress((void**)&P.ol, g_ol);
    cudaGetSymbolAddress((void**)&P.wbth, g_wbth); cudaGetSymbolAddress((void**)&P.wbtl, g_wbtl);
    cudaGetSymbolAddress((void**)&P.hh, g_hh);     cudaGetSymbolAddress((void**)&P.hl, g_hl);

    float* out = (float*)d_out;
    float* pp_out = out + (out_size - Bsz);

    const long long MD = (long long)Mrows * Dm;
    const int NXD2 = M2 * Dm;

    // 0. one-time splits
    split_k<<<(Mrows*IDIM/4 + 255)/256, 256>>>(x1i, P.x1ih, P.x1il, Mrows*IDIM/4);
    split_k<<<(Mrows*IDIM/4 + 255)/256, 256>>>(x2i, P.x2ih, P.x2il, Mrows*IDIM/4);
    split_k<<<(Dm*IDIM/4 + 255)/256, 256>>>(proj_w, P.wph, P.wpl, Dm*IDIM/4);
    split_k<<<(3*Dm*Dm/4 + 255)/256, 256>>>(mha_in_w, P.miwh, P.miwl, 3*Dm*Dm/4);
    split_k<<<(Dm*Dm/4 + 255)/256, 256>>>(mha_out_w, P.mowh, P.mowl, Dm*Dm/4);
    split_k<<<(3*Dm*Dm/4 + 255)/256, 256>>>(ca_in_w, P.ciwh, P.ciwl, 3*Dm*Dm/4);
    split_k<<<(Dm*Dm/4 + 255)/256, 256>>>(ca_out_w, P.cowh, P.cowl, Dm*Dm/4);
    {
        dim3 g(HALFc/32, Dm/32, NBINS);
        transpose_split_k<<<g, dim3(32,8)>>>(Wbins, P.wbth, P.wbtl);
    }

    // 1. input projections
    gemm(128, P.x1ih, P.x1il, P.wph, P.wpl, P.xf, P.xh, P.xl,
         Mrows, Dm, IDIM, IDIM, IDIM, Dm, 0,0,0,0,0,0, 1,1, proj_b, 1, 1.f, 0, nullptr, 3);
    gemm(128, P.x2ih, P.x2il, P.wph, P.wpl, P.xf + MD, P.xh + MD, P.xl + MD,
         Mrows, Dm, IDIM, IDIM, IDIM, Dm, 0,0,0,0,0,0, 1,1, proj_b, 1, 1.f, 0, nullptr, 3);

    // 2. self-attention (+residual)
    run_mha(P, P.xh, P.xl, P.xh, P.xl, P.miwh, P.miwl, mha_in_b,
            P.mowh, P.mowl, mha_out_b, P.xf, false);

    // 3. tanh -> planes
    tanh_split_k<<<(NXD2/4 + 255)/256, 256>>>(P.xf, P.th, P.tl, NXD2/4);

    // 4. cross-attention (+residual), swapped KV
    run_mha(P, P.th, P.tl, P.th, P.tl, P.ciwh, P.ciwl, ca_in_b,
            P.cowh, P.cowl, ca_out_b, P.xf, true);

    // 5. tanh -> planes
    tanh_split_k<<<(NXD2/4 + 255)/256, 256>>>(P.xf, P.th, P.tl, NXD2/4);

    // 6. h = tanh(x @ Wbins)
    gemm(128, P.th, P.tl, P.wbth, P.wbtl, nullptr, P.hh, P.hl,
         Lsz, HALFc, Dm, Dm, Dm, HALFc,
         (long long)Lsz*Dm, 0, 0, (long long)HALFc*Dm,
         (long long)NBINS*Lsz*HALFc, (long long)Lsz*HALFc, 2*Bsz, NBINS,
         nullptr, 0, 1.f, 1, nullptr, 2);

    // 7+8. per-b: cm GEMM into reused slice, then smoothing (L2-hot raw)
    {
        const long long hhalf = (long long)Bsz*NBINS*Lsz*HALFc;
        const long long hbs   = (long long)NBINS*Lsz*HALFc;   // per-b h stride
        for (int b = 0; b < Bsz; b++) {
            gemm(128, P.hh + b*hbs, P.hl + b*hbs,
                 P.hh + hhalf + b*hbs, P.hl + hhalf + b*hbs,
                 P.cmraw, nullptr, nullptr,
                 Lsz, Lsz, HALFc, HALFc, HALFc, Lsz,
                 0, (long long)Lsz*HALFc, 0, (long long)Lsz*HALFc,
                 0, (long long)Lsz*Lsz, 1, NBINS,
                 nullptr, 0, 1.f, 0, nullptr, 1);
            smooth_b<<<(Lsz*Lsz/4 + 255)/256, 256>>>(
                P.cmraw, smooth, agg,
                out + (size_t)b*NBINS*Lsz*Lsz,
                P.cm1 + (size_t)b*Lsz*Lsz);
        }
    }

    // 9. integral image
    colsum_k<<<(Bsz*Lsz + 255) / 256, 256>>>(P.cm1, P.cs);
    rowsum_k<<<(Bsz*Lsz + 255) / 256, 256>>>(P.cs, P.I);

    // 10. head
    finalize_k<<<Bsz, 128>>>(P.I, Lmat, biasp, pp_out);
}

// round 15
// speedup vs baseline: 1.0226x; 1.0226x over previous
#include <cuda_runtime.h>
#include <cuda_bf16.h>
#include <math.h>
#include <stdint.h>

#define Bsz 8
#define Lsz 512
#define IDIM 1024
#define Dm 512
#define Hh 8
#define DH 64
#define NBINS 25
#define PWc 10
#define HALFc 256
#define ISZ 513

#define Mrows (Bsz*Lsz)          // 4096
#define M2 (2*Mrows)             // 8192 combined

typedef __nv_bfloat16 bf16;

// ------------------------- fp32 scratch -------------------------
__device__ float g_xf [(size_t)M2*Dm];
__device__ float g_cmraw[(size_t)Bsz*NBINS*Lsz*Lsz];
__device__ float g_cm1[Bsz*Lsz*Lsz];
__device__ float g_cs [Bsz*Lsz*Lsz];
__device__ float g_I  [Bsz*ISZ*ISZ];

// ------------------------- bf16 hi/lo planes -------------------------
__device__ bf16 g_x1ih[Mrows*IDIM], g_x1il[Mrows*IDIM];
__device__ bf16 g_x2ih[Mrows*IDIM], g_x2il[Mrows*IDIM];
__device__ bf16 g_wph[Dm*IDIM],  g_wpl[Dm*IDIM];
__device__ bf16 g_miwh[3*Dm*Dm], g_miwl[3*Dm*Dm];
__device__ bf16 g_mowh[Dm*Dm],   g_mowl[Dm*Dm];
__device__ bf16 g_ciwh[3*Dm*Dm], g_ciwl[3*Dm*Dm];
__device__ bf16 g_cowh[Dm*Dm],   g_cowl[Dm*Dm];
__device__ bf16 g_xh[(size_t)M2*Dm], g_xl[(size_t)M2*Dm];
__device__ bf16 g_th[(size_t)M2*Dm], g_tl[(size_t)M2*Dm];
__device__ bf16 g_qkh[(size_t)M2*2*Dm], g_qkl[(size_t)M2*2*Dm];   // Q | K combined
__device__ bf16 g_vth[(size_t)Dm*M2], g_vtl[(size_t)Dm*M2];
__device__ bf16 g_oh[(size_t)M2*Dm], g_ol[(size_t)M2*Dm];
__device__ bf16 g_wbth[NBINS*HALFc*Dm], g_wbtl[NBINS*HALFc*Dm];
__device__ bf16 g_hh[(size_t)2*Bsz*NBINS*Lsz*HALFc];
__device__ bf16 g_hl[(size_t)2*Bsz*NBINS*Lsz*HALFc];

// ------------------------- helpers -------------------------
__device__ __forceinline__ uint32_t smem_u32(const void* p){
    uint32_t a;
    asm("{ .reg .u64 t; cvta.to.shared.u64 t, %1; cvt.u32.u64 %0, t; }" : "=r"(a) : "l"(p));
    return a;
}
__device__ __forceinline__ void cp16(uint32_t dst, const void* src){
    asm volatile("cp.async.cg.shared.global [%0], [%1], 16;" :: "r"(dst), "l"(src));
}
#define CP_COMMIT() asm volatile("cp.async.commit_group;" ::: "memory")
#define CP_WAIT(n)  asm volatile("cp.async.wait_group %0;" :: "n"(n) : "memory")

__device__ __forceinline__ uint4 ldm4(uint32_t addr){
    uint4 r;
    asm volatile("ldmatrix.sync.aligned.m8n8.x4.shared.b16 {%0,%1,%2,%3}, [%4];"
        : "=r"(r.x), "=r"(r.y), "=r"(r.z), "=r"(r.w) : "r"(addr));
    return r;
}
__device__ __forceinline__ void mma_bf16(float c[4], uint4 a, uint32_t b0, uint32_t b1){
    asm volatile("mma.sync.aligned.m16n8k16.row.col.f32.bf16.bf16.f32 "
        "{%0,%1,%2,%3}, {%4,%5,%6,%7}, {%8,%9}, {%0,%1,%2,%3};"
        : "+f"(c[0]), "+f"(c[1]), "+f"(c[2]), "+f"(c[3])
        : "r"(a.x), "r"(a.y), "r"(a.z), "r"(a.w), "r"(b0), "r"(b1));
}

// fp32 -> bf16 hi (truncate) / lo (rn of remainder)
__device__ __forceinline__ void cvt_hilo(float4 v, uint2& hi, uint2& lo){
    uint32_t ux = __float_as_uint(v.x), uy = __float_as_uint(v.y),
             uz = __float_as_uint(v.z), uw = __float_as_uint(v.w);
    float hx = __uint_as_float(ux & 0xffff0000u);
    float hy = __uint_as_float(uy & 0xffff0000u);
    float hz = __uint_as_float(uz & 0xffff0000u);
    float hw = __uint_as_float(uw & 0xffff0000u);
    asm("prmt.b32 %0, %1, %2, 0x7632;" : "=r"(hi.x) : "r"(ux), "r"(uy));
    asm("prmt.b32 %0, %1, %2, 0x7632;" : "=r"(hi.y) : "r"(uz), "r"(uw));
    float lx = v.x - hx, ly = v.y - hy, lz = v.z - hz, lw = v.w - hw;
    asm("cvt.rn.bf16x2.f32 %0, %1, %2;" : "=r"(lo.x) : "f"(ly), "f"(lx));
    asm("cvt.rn.bf16x2.f32 %0, %1, %2;" : "=r"(lo.y) : "f"(lw), "f"(lz));
}
__device__ __forceinline__ void cvt_hilo2(float v0, float v1, uint32_t& h, uint32_t& l){
    uint32_t u0 = __float_as_uint(v0), u1 = __float_as_uint(v1);
    asm("prmt.b32 %0, %1, %2, 0x7632;" : "=r"(h) : "r"(u0), "r"(u1));
    float h0 = __uint_as_float(u0 & 0xffff0000u);
    float h1 = __uint_as_float(u1 & 0xffff0000u);
    asm("cvt.rn.bf16x2.f32 %0, %1, %2;" : "=r"(l) : "f"(v1-h1), "f"(v0-h0));
}
__device__ __forceinline__ void split1(float x, bf16* h, bf16* l){
    uint32_t ux = __float_as_uint(x);
    __nv_bfloat16_raw r; r.x = (unsigned short)(ux >> 16);
    *h = r;
    float hf = __uint_as_float(ux & 0xffff0000u);
    *l = __float2bfloat16(x - hf);
}

// ------------------------- mma.sync GEMM -------------------------
template<int BN>
__global__ void __launch_bounds__(256, 2)
gemm_mma(const bf16* __restrict__ Ah, const bf16* __restrict__ Al,
         const bf16* __restrict__ Bh, const bf16* __restrict__ Bl,
         float* __restrict__ C, bf16* __restrict__ Ch, bf16* __restrict__ Cl,
         int K, int lda, int ldb, int ldc,
         long long sA1, long long sA2, long long sB1, long long sB2,
         long long sC1, long long sC2, int batch2,
         const float* __restrict__ bias, int biasMode, float alpha, int act,
         const float* __restrict__ Cres, int outMode)
{
    constexpr int BM = 128, BK = 32;
    constexpr int ROWB = BK*2 + 16;
    constexpr int APL = BM * ROWB;
    constexpr int BPL = BN * ROWB;
    constexpr int STAGE = 2*APL + 2*BPL;
    constexpr int WN = BN / 2;
    constexpr int NB = WN / 8;
    constexpr int KCH = BK / 8;
    constexpr int NCHUNK = (2*BM + 2*BN) * KCH;

    extern __shared__ __align__(128) char smem[];
    const uint32_t sb = smem_u32(smem);

    const int z = blockIdx.z, z1 = z / batch2, z2 = z % batch2;
    const long long aoff = z1*sA1 + z2*sA2;
    const long long boff = z1*sB1 + z2*sB2;
    const long long coff = z1*sC1 + z2*sC2;
    Ah += aoff; Al += aoff;
    Bh += boff; Bl += boff;

    const int m0 = blockIdx.y * BM;
    const int n0 = blockIdx.x * BN;
    const int tid = threadIdx.x;
    const int wid = tid >> 5, lane = tid & 31;
    const int wm = wid >> 1, wn = wid & 1;
    const int mbase = wm * 32;
    const int nbase = wn * WN;

    float acc[2][NB][4];
    #pragma unroll
    for (int i = 0; i < 2; i++)
        #pragma unroll
        for (int j = 0; j < NB; j++)
            #pragma unroll
            for (int u = 0; u < 4; u++) acc[i][j][u] = 0.f;

    const int NC = K / BK;

    auto stage_copy = [&](int c, int s){
        const uint32_t st = sb + (uint32_t)s * STAGE;
        #pragma unroll
        for (int i = 0; i < NCHUNK/256; i++) {
            int idx = tid + i*256;
            const bf16* src; uint32_t dst;
            if (idx < 2*BM*KCH) {
                int p = idx / (BM*KCH); int rem = idx - p*BM*KCH;
                int r = rem >> 2, cc = rem & 3;
                src = (p ? Al : Ah) + (long long)(m0+r)*lda + c*BK + cc*8;
                dst = st + p*APL + r*ROWB + cc*16;
            } else {
                int j = idx - 2*BM*KCH;
                int p = j / (BN*KCH); int rem = j - p*BN*KCH;
                int r = rem >> 2, cc = rem & 3;
                src = (p ? Bl : Bh) + (long long)(n0+r)*ldb + c*BK + cc*8;
                dst = st + 2*APL + p*BPL + r*ROWB + cc*16;
            }
            cp16(dst, src);
        }
    };

    auto compute = [&](int s){
        const uint32_t st = sb + (uint32_t)s * STAGE;
        const uint32_t ab = st;
        const uint32_t bb = st + 2*APL;
        const int arow = mbase + (lane & 15);
        const int akoff = ((lane >> 4) & 1) * 16;
        const int brow0 = nbase + (lane & 7) + ((lane >> 4) & 1) * 8;
        const int bkoff = ((lane >> 3) & 1) * 16;
        #pragma unroll
        for (int ks = 0; ks < BK/16; ks++) {
            const int kb = ks * 32;
            uint4 a[2][2];
            #pragma unroll
            for (int p = 0; p < 2; p++)
                #pragma unroll
                for (int mb = 0; mb < 2; mb++)
                    a[p][mb] = ldm4(ab + p*APL + (arow + mb*16)*ROWB + kb + akoff);
            #pragma unroll
            for (int nb2 = 0; nb2 < NB/2; nb2++) {
                uint4 b0 = ldm4(bb + (brow0 + nb2*16)*ROWB + kb + bkoff);
                uint4 b1 = ldm4(bb + BPL + (brow0 + nb2*16)*ROWB + kb + bkoff);
                #pragma unroll
                for (int mb = 0; mb < 2; mb++) {
                    float* c0 = acc[mb][2*nb2];
                    float* c1 = acc[mb][2*nb2+1];
                    mma_bf16(c0, a[0][mb], b0.x, b0.y);
                    mma_bf16(c1, a[0][mb], b0.z, b0.w);
                    mma_bf16(c0, a[0][mb], b1.x, b1.y);
                    mma_bf16(c1, a[0][mb], b1.z, b1.w);
                    mma_bf16(c0, a[1][mb], b0.x, b0.y);
                    mma_bf16(c1, a[1][mb], b0.z, b0.w);
                }
            }
        }
    };

    stage_copy(0, 0);
    CP_COMMIT();
    for (int c = 0; c < NC; c++) {
        CP_WAIT(0);
        __syncthreads();
        if (c + 1 < NC) { stage_copy(c + 1, (c + 1) & 1); CP_COMMIT(); }
        compute(c & 1);
    }

    const int g = lane >> 2, t = lane & 3;
    #pragma unroll
    for (int mb = 0; mb < 2; mb++) {
        #pragma unroll
        for (int half = 0; half < 2; half++) {
            const int row = m0 + mbase + mb*16 + g + half*8;
            const long long rowo = coff + (long long)row * ldc;
            float brow = (biasMode == 2) ? bias[row] : 0.f;
            #pragma unroll
            for (int nb = 0; nb < NB; nb++) {
                const int col = n0 + nbase + nb*8 + 2*t;
                float v0 = acc[mb][nb][half*2+0] * alpha;
                float v1 = acc[mb][nb][half*2+1] * alpha;
                if (biasMode == 1) {
                    float2 bb = *reinterpret_cast<const float2*>(&bias[col]);
                    v0 += bb.x; v1 += bb.y;
                } else if (biasMode == 2) {
                    v0 += brow; v1 += brow;
                }
                if (Cres) {
                    float2 rr = *reinterpret_cast<const float2*>(&Cres[rowo + col]);
                    v0 += rr.x; v1 += rr.y;
                }
                if (act) { v0 = tanhf(v0); v1 = tanhf(v1); }
                if (outMode & 1)
                    *reinterpret_cast<float2*>(&C[rowo + col]) = make_float2(v0, v1);
                if (outMode & 2) {
                    uint32_t h, l;
                    cvt_hilo2(v0, v1, h, l);
                    *reinterpret_cast<uint32_t*>(&Ch[rowo + col]) = h;
                    *reinterpret_cast<uint32_t*>(&Cl[rowo + col]) = l;
                }
            }
        }
    }
}

// ------------------------- fused attention -------------------------
// Q and K live in the combined qk buffer (row stride 2*Dm; K at col offset Dm).
__global__ void __launch_bounds__(256, 1)
fused_attn(const bf16* __restrict__ QKh, const bf16* __restrict__ QKl,
           const bf16* __restrict__ Vth, const bf16* __restrict__ Vtl,
           bf16* __restrict__ Oh, bf16* __restrict__ Ol)
{
    constexpr int LDQ = 2*Dm;                // 1024
    constexpr int QROWB = 144;
    constexpr int KROWB = 144;
    constexpr int VROWB = 272;
    constexpr int QPL = 128 * QROWB;
    constexpr int KPL = 128 * KROWB;
    constexpr int VPL = 64 * VROWB;

    extern __shared__ __align__(128) char smem[];
    const uint32_t sbm = smem_u32(smem);
    const uint32_t qb = sbm;
    const uint32_t kbb = qb + 2*QPL;
    const uint32_t vb = kbb + 2*KPL;
    float* maxred = reinterpret_cast<float*>(smem + 2*QPL + 2*KPL + 2*VPL);
    float* sumred = maxred + 256;
    float* oex    = sumred + 256;

    const int tid = threadIdx.x;
    const int wid = tid >> 5, lane = tid & 31;
    const int wm = wid >> 1, wn = wid & 1;
    const int g = lane >> 2, t = lane & 3;

    const int sbatch = blockIdx.y >> 3;
    const int h = blockIdx.y & 7;
    const long long tb = (long long)sbatch * Lsz;
    const int q0 = blockIdx.x * 128;

    #pragma unroll
    for (int i = 0; i < 8; i++) {
        int idx = tid + i*256;
        int p = idx >> 10, rem = idx & 1023;
        int r = rem >> 3, cc = rem & 7;
        const bf16* src = (p ? QKl : QKh) + (tb + q0 + r)*LDQ + h*DH + cc*8;
        cp16(qb + p*QPL + r*QROWB + cc*16, src);
    }

    auto stage_kv = [&](int kt){
        #pragma unroll
        for (int i = 0; i < 8; i++) {
            int idx = tid + i*256;
            int p = idx >> 10, rem = idx & 1023;
            int r = rem >> 3, cc = rem & 7;
            const bf16* src = (p ? QKl : QKh) + (tb + kt*128 + r)*LDQ + Dm + h*DH + cc*8;
            cp16(kbb + p*KPL + r*KROWB + cc*16, src);
        }
        #pragma unroll
        for (int i = 0; i < 8; i++) {
            int idx = tid + i*256;
            int p = idx >> 10, rem = idx & 1023;
            int r = rem >> 4, cc = rem & 15;
            const bf16* src = (p ? Vtl : Vth) + (long long)(h*DH + r)*M2 + tb + kt*128 + cc*8;
            cp16(vb + p*VPL + r*VROWB + cc*16, src);
        }
    };

    float oacc[2][8][4];
    float sacc[2][8][4];
    float mrow[2][2], lrow[2][2];
    #pragma unroll
    for (int mb = 0; mb < 2; mb++) {
        #pragma unroll
        for (int nb = 0; nb < 8; nb++)
            #pragma unroll
            for (int u = 0; u < 4; u++) oacc[mb][nb][u] = 0.f;
        mrow[mb][0] = -1e30f; mrow[mb][1] = -1e30f;
        lrow[mb][0] = 0.f;    lrow[mb][1] = 0.f;
    }

    stage_kv(0);
    CP_COMMIT(); CP_WAIT(0);
    __syncthreads();

    const int arow  = wm*32 + (lane & 15);
    const int akoff = ((lane >> 4) & 1) * 16;
    const int brow0 = wn*64 + (lane & 7) + ((lane >> 4) & 1) * 8;
    const int bkoff = ((lane >> 3) & 1) * 16;
    const int dbrow0 = (lane & 7) + ((lane >> 4) & 1) * 8;

    for (int kt = 0; kt < 4; kt++) {
        #pragma unroll
        for (int mb = 0; mb < 2; mb++)
            #pragma unroll
            for (int nb = 0; nb < 8; nb++)
                #pragma unroll
                for (int u = 0; u < 4; u++) sacc[mb][nb][u] = 0.f;
        #pragma unroll
        for (int ks = 0; ks < 4; ks++) {
            const int kb2 = ks * 32;
            uint4 a[2][2];
            #pragma unroll
            for (int p = 0; p < 2; p++)
                #pragma unroll
                for (int mb = 0; mb < 2; mb++)
                    a[p][mb] = ldm4(qb + p*QPL + (arow + mb*16)*QROWB + kb2 + akoff);
            #pragma unroll
            for (int nb2 = 0; nb2 < 4; nb2++) {
                uint4 b0 = ldm4(kbb + (brow0 + nb2*16)*KROWB + kb2 + bkoff);
                uint4 b1 = ldm4(kbb + KPL + (brow0 + nb2*16)*KROWB + kb2 + bkoff);
                #pragma unroll
                for (int mb = 0; mb < 2; mb++) {
                    float* c0 = sacc[mb][2*nb2];
                    float* c1 = sacc[mb][2*nb2+1];
                    mma_bf16(c0, a[0][mb], b0.x, b0.y);
                    mma_bf16(c1, a[0][mb], b0.z, b0.w);
                    mma_bf16(c0, a[0][mb], b1.x, b1.y);
                    mma_bf16(c1, a[0][mb], b1.z, b1.w);
                    mma_bf16(c0, a[1][mb], b0.x, b0.y);
                    mma_bf16(c1, a[1][mb], b0.z, b0.w);
                }
            }
        }
        #pragma unroll
        for (int mb = 0; mb < 2; mb++)
            #pragma unroll
            for (int nb = 0; nb < 8; nb++)
                #pragma unroll
                for (int u = 0; u < 4; u++) sacc[mb][nb][u] *= 0.125f;
        #pragma unroll
        for (int mb = 0; mb < 2; mb++)
            #pragma unroll
            for (int half = 0; half < 2; half++) {
                float mx = -1e30f;
                #pragma unroll
                for (int nb = 0; nb < 8; nb++) {
                    mx = fmaxf(mx, sacc[mb][nb][half*2]);
                    mx = fmaxf(mx, sacc[mb][nb][half*2+1]);
                }
                mx = fmaxf(mx, __shfl_xor_sync(0xffffffffu, mx, 1));
                mx = fmaxf(mx, __shfl_xor_sync(0xffffffffu, mx, 2));
                if (t == 0) maxred[wn*128 + wm*32 + mb*16 + g + half*8] = mx;
            }
        __syncthreads();
        #pragma unroll
        for (int mb = 0; mb < 2; mb++)
            #pragma unroll
            for (int half = 0; half < 2; half++) {
                const int r = wm*32 + mb*16 + g + half*8;
                float mt = fmaxf(maxred[r], maxred[128 + r]);
                float mnew = fmaxf(mrow[mb][half], mt);
                float corr = expf(mrow[mb][half] - mnew);
                mrow[mb][half] = mnew;
                lrow[mb][half] *= corr;
                float sum = 0.f;
                #pragma unroll
                for (int nb = 0; nb < 8; nb++) {
                    float p0 = expf(sacc[mb][nb][half*2]   - mnew);
                    float p1 = expf(sacc[mb][nb][half*2+1] - mnew);
                    sacc[mb][nb][half*2]   = p0;
                    sacc[mb][nb][half*2+1] = p1;
                    sum += p0 + p1;
                    oacc[mb][nb][half*2]   *= corr;
                    oacc[mb][nb][half*2+1] *= corr;
                }
                sum += __shfl_xor_sync(0xffffffffu, sum, 1);
                sum += __shfl_xor_sync(0xffffffffu, sum, 2);
                if (t == 0) sumred[wn*128 + r] = sum;
            }
        __syncthreads();
        #pragma unroll
        for (int mb = 0; mb < 2; mb++)
            #pragma unroll
            for (int half = 0; half < 2; half++) {
                const int r = wm*32 + mb*16 + g + half*8;
                lrow[mb][half] += sumred[r] + sumred[128 + r];
            }
        #pragma unroll
        for (int ksp = 0; ksp < 4; ksp++) {
            uint4 pah[2], pal[2];
            #pragma unroll
            for (int mb = 0; mb < 2; mb++) {
                float* b0p = sacc[mb][2*ksp];
                float* b1p = sacc[mb][2*ksp+1];
                cvt_hilo2(b0p[0], b0p[1], pah[mb].x, pal[mb].x);
                cvt_hilo2(b0p[2], b0p[3], pah[mb].y, pal[mb].y);
                cvt_hilo2(b1p[0], b1p[1], pah[mb].z, pal[mb].z);
                cvt_hilo2(b1p[2], b1p[3], pah[mb].w, pal[mb].w);
            }
            const int vcol = (wn*64 + ksp*16)*2 + bkoff;
            #pragma unroll
            for (int nb2 = 0; nb2 < 4; nb2++) {
                uint4 bh = ldm4(vb + (dbrow0 + nb2*16)*VROWB + vcol);
                uint4 bl = ldm4(vb + VPL + (dbrow0 + nb2*16)*VROWB + vcol);
                #pragma unroll
                for (int mb = 0; mb < 2; mb++) {
                    float* c0 = oacc[mb][2*nb2];
                    float* c1 = oacc[mb][2*nb2+1];
                    mma_bf16(c0, pah[mb], bh.x, bh.y);
                    mma_bf16(c1, pah[mb], bh.z, bh.w);
                    mma_bf16(c0, pah[mb], bl.x, bl.y);
                    mma_bf16(c1, pah[mb], bl.z, bl.w);
                    mma_bf16(c0, pal[mb], bh.x, bh.y);
                    mma_bf16(c1, pal[mb], bh.z, bh.w);
                }
            }
        }
        __syncthreads();
        if (kt < 3) {
            stage_kv(kt + 1);
            CP_COMMIT(); CP_WAIT(0);
            __syncthreads();
        }
    }

    if (wn == 1) {
        #pragma unroll
        for (int mb = 0; mb < 2; mb++)
            #pragma unroll
            for (int half = 0; half < 2; half++) {
                const int r = wm*32 + mb*16 + g + half*8;
                #pragma unroll
                for (int nb = 0; nb < 8; nb++) {
                    oex[r*64 + nb*8 + 2*t]     = oacc[mb][nb][half*2];
                    oex[r*64 + nb*8 + 2*t + 1] = oacc[mb][nb][half*2+1];
                }
            }
    }
    __syncthreads();
    if (wn == 0) {
        #pragma unroll
        for (int mb = 0; mb < 2; mb++)
            #pragma unroll
            for (int half = 0; half < 2; half++) {
                const int r = wm*32 + mb*16 + g + half*8;
                const float inv = 1.f / lrow[mb][half];
                const long long rowo = (tb + q0 + r)*Dm + h*DH;
                #pragma unroll
                for (int nb = 0; nb < 8; nb++) {
                    const int col = nb*8 + 2*t;
                    float v0 = (oacc[mb][nb][half*2]   + oex[r*64 + col])     * inv;
                    float v1 = (oacc[mb][nb][half*2+1] + oex[r*64 + col + 1]) * inv;
                    uint32_t hh, ll;
                    cvt_hilo2(v0, v1, hh, ll);
                    *reinterpret_cast<uint32_t*>(&Oh[rowo + col]) = hh;
                    *reinterpret_cast<uint32_t*>(&Ol[rowo + col]) = ll;
                }
            }
    }
}

// ------------------------- converts -------------------------
__global__ void split_k(const float* __restrict__ in, bf16* __restrict__ oh,
                        bf16* __restrict__ ol, int n4)
{
    int i = blockIdx.x * blockDim.x + threadIdx.x;
    if (i >= n4) return;
    float4 v = reinterpret_cast<const float4*>(in)[i];
    uint2 h, l; cvt_hilo(v, h, l);
    reinterpret_cast<uint2*>(oh)[i] = h;
    reinterpret_cast<uint2*>(ol)[i] = l;
}
__global__ void tanh_split_k(const float* __restrict__ in, bf16* __restrict__ oh,
                             bf16* __restrict__ ol, int n4)
{
    int i = blockIdx.x * blockDim.x + threadIdx.x;
    if (i >= n4) return;
    float4 v = reinterpret_cast<const float4*>(in)[i];
    v.x = tanhf(v.x); v.y = tanhf(v.y); v.z = tanhf(v.z); v.w = tanhf(v.w);
    uint2 h, l; cvt_hilo(v, h, l);
    reinterpret_cast<uint2*>(oh)[i] = h;
    reinterpret_cast<uint2*>(ol)[i] = l;
}
__global__ void transpose_split_k(const float* __restrict__ in,
                                  bf16* __restrict__ oh, bf16* __restrict__ ol)
{
    __shared__ float tile[32][33];
    int n = blockIdx.z;
    int k0 = blockIdx.x * 32, d0 = blockIdx.y * 32;
    in += (size_t)n * Dm * HALFc;
    oh += (size_t)n * HALFc * Dm;
    ol += (size_t)n * HALFc * Dm;
    int tx = threadIdx.x, ty = threadIdx.y;
    #pragma unroll
    for (int i = ty; i < 32; i += 8)
        tile[i][tx] = in[(d0 + i) * HALFc + k0 + tx];
    __syncthreads();
    #pragma unroll
    for (int i = ty; i < 32; i += 8) {
        bf16 h, l; split1(tile[tx][i], &h, &l);
        oh[(k0 + i) * Dm + d0 + tx] = h;
        ol[(k0 + i) * Dm + d0 + tx] = l;
    }
}

// ------------------------- bin smoothing + aggregate (float4) -------------------------
__global__ void __launch_bounds__(256)
smooth_k4(const float* __restrict__ raw, const float* __restrict__ sm,
          const float* __restrict__ agg, float* __restrict__ cm_out,
          float* __restrict__ cm1)
{
    const int tot4 = Bsz * Lsz * Lsz / 4;
    int idx = blockIdx.x * blockDim.x + threadIdx.x;
    if (idx >= tot4) return;
    const int PS = Lsz * Lsz / 4;
    int b   = idx / PS;
    int rem = idx % PS;

    const float4* base = reinterpret_cast<const float4*>(raw)
                       + (size_t)b * NBINS * PS + rem;
    float4 rv[NBINS];
    #pragma unroll
    for (int n = 0; n < NBINS; n++) rv[n] = base[(size_t)n * PS];

    float sw[5];
    #pragma unroll
    for (int k = 0; k < 5; k++) sw[k] = sm[k];

    float4* outb = reinterpret_cast<float4*>(cm_out) + (size_t)b * NBINS * PS + rem;
    float4 acc = make_float4(0.f, 0.f, 0.f, 0.f);
    #pragma unroll
    for (int n = 0; n < NBINS; n++) {
        float4 v = make_float4(0.f, 0.f, 0.f, 0.f);
        #pragma unroll
        for (int k = 0; k < 5; k++) {
            int m = n + k - 2;
            if (m >= 0 && m < NBINS) {
                v.x += sw[k] * rv[m].x;
                v.y += sw[k] * rv[m].y;
                v.z += sw[k] * rv[m].z;
                v.w += sw[k] * rv[m].w;
            }
        }
        outb[(size_t)n * PS] = v;
        float a = agg[n];
        acc.x += a * v.x; acc.y += a * v.y;
        acc.z += a * v.z; acc.w += a * v.w;
    }
    float4 o = make_float4(tanhf(acc.x), tanhf(acc.y), tanhf(acc.z), tanhf(acc.w));
    reinterpret_cast<float4*>(cm1)[idx] = o;
}

// ------------------------- integral image + head -------------------------
__global__ void colsum_k(const float* __restrict__ cm1, float* __restrict__ cs)
{
    int t = blockIdx.x * blockDim.x + threadIdx.x;
    if (t >= Bsz * Lsz) return;
    int b = t / Lsz, j = t % Lsz;
    const float* src = cm1 + (long long)b * Lsz * Lsz + j;
    float* dst       = cs  + (long long)b * Lsz * Lsz + j;
    float acc = 0.f;
    for (int i = 0; i < Lsz; i++) {
        acc += src[(long long)i * Lsz];
        dst[(long long)i * Lsz] = acc;
    }
}
__global__ void rowsum_k(const float* __restrict__ cs, float* __restrict__ I)
{
    int t = blockIdx.x * blockDim.x + threadIdx.x;
    if (t >= Bsz * Lsz) return;
    int b = t / Lsz, i = t % Lsz;
    const float* src = cs + (long long)b * Lsz * Lsz + (long long)i * Lsz;
    float* row = I + (long long)b * ISZ * ISZ + (long long)(i + 1) * ISZ;
    float acc = 0.f;
    row[0] = 0.f;
    for (int j = 0; j < Lsz; j++) { acc += src[j]; row[j + 1] = acc; }
    if (i == 0) {
        float* r0 = I + (long long)b * ISZ * ISZ;
        for (int c = 0; c < ISZ; c++) r0[c] = 0.f;
    }
}
__global__ void finalize_k(const float* __restrict__ I, const float* __restrict__ Lmat,
                           const float* __restrict__ biasp, float* __restrict__ pp)
{
    int b = blockIdx.x;
    __shared__ float terms[128];
    int t = threadIdx.x;
    float val = 0.f;
    if (t < PWc * PWc) {
        int p = t / PWc, q = t % PWc;
        const float* Ib = I + (long long)b * ISZ * ISZ;
        const int Hp = Lsz - PWc + 1;
        float w = Ib[(Hp + p) * ISZ + (Hp + q)] - Ib[(Hp + p) * ISZ + q]
                - Ib[p * ISZ + (Hp + q)]       + Ib[p * ISZ + q];
        val = tanhf(w) * Lmat[t];
    }
    terms[t] = val;
    __syncthreads();
    if (t == 0) {
        float s = 0.f;
        for (int i = 0; i < PWc * PWc; i++) s += terms[i];
        pp[b] = 1.0f / (1.0f + expf(-(s + biasp[0])));
    }
}

// ------------------------- host-side -------------------------
static int SMEM_TOTAL_BYTES(int BN) { return 2 * (2*128 + 2*BN) * (32*2 + 16); }
static int FA_SMEM() { return 2*128*144 + 2*128*144 + 2*64*272 + (256 + 256 + 128*64)*4; }

static void gemm(int BN, const bf16* Ah, const bf16* Al, const bf16* Bh, const bf16* Bl,
                 float* C, bf16* Ch, bf16* Cl,
                 int M, int N, int K, int lda, int ldb, int ldc,
                 long long sA1, long long sA2, long long sB1, long long sB2,
                 long long sC1, long long sC2, int batch1, int batch2,
                 const float* bias, int biasMode, float alpha, int act,
                 const float* Cres, int outMode)
{
    dim3 grid(N / BN, M / 128, batch1 * batch2);
    if (BN == 128)
        gemm_mma<128><<<grid, 256, SMEM_TOTAL_BYTES(128)>>>(Ah, Al, Bh, Bl, C, Ch, Cl,
            K, lda, ldb, ldc, sA1, sA2, sB1, sB2, sC1, sC2, batch2,
            bias, biasMode, alpha, act, Cres, outMode);
    else
        gemm_mma<64><<<grid, 256, SMEM_TOTAL_BYTES(64)>>>(Ah, Al, Bh, Bl, C, Ch, Cl,
            K, lda, ldb, ldc, sA1, sA2, sB1, sB2, sC1, sC2, batch2,
            bias, biasMode, alpha, act, Cres, outMode);
}

struct Ptrs {
    float *xf, *cmraw, *cm1, *cs, *I;
    bf16 *x1ih,*x1il,*x2ih,*x2il,*wph,*wpl,*miwh,*miwl,*mowh,*mowl,*ciwh,*ciwl,*cowh,*cowl;
    bf16 *xh,*xl,*th,*tl,*qkh,*qkl,*vth,*vtl,*oh,*ol;
    bf16 *wbth,*wbtl,*hh,*hl;
};

static void run_mha(const Ptrs& P,
                    const bf16* qsh, const bf16* qsl,
                    const bf16* kvh, const bf16* kvl,
                    const bf16* iwh, const bf16* iwl, const float* in_b,
                    const bf16* owh, const bf16* owl, const float* out_b,
                    float* target, bool swapKV)
{
    const long long MD = (long long)Mrows * Dm;
    if (!swapKV) {
        // fused Q+K projection: N=1024 into combined qk (ldc = 2*Dm)
        gemm(128, qsh, qsl, iwh, iwl, nullptr, P.qkh, P.qkl,
             M2, 2*Dm, Dm, Dm, Dm, 2*Dm, 0,0,0,0,0,0, 1,1, in_b, 1, 1.f, 0, nullptr, 2);
        gemm(128, iwh + 2*Dm*Dm, iwl + 2*Dm*Dm, kvh, kvl, nullptr, P.vth, P.vtl,
             Dm, M2, Dm, Dm, Dm, M2, 0,0,0,0,0,0, 1,1, in_b + 2*Dm, 2, 1.f, 0, nullptr, 2);
    } else {
        gemm(128, qsh, qsl, iwh, iwl, nullptr, P.qkh, P.qkl,
             M2, Dm, Dm, Dm, Dm, 2*Dm, 0,0,0,0,0,0, 1,1, in_b, 1, 1.f, 0, nullptr, 2);
        gemm(128, kvh, kvl, iwh + Dm*Dm, iwl + Dm*Dm, nullptr,
             P.qkh + Dm + (long long)Mrows*2*Dm, P.qkl + Dm + (long long)Mrows*2*Dm,
             Mrows, Dm, Dm, Dm, Dm, 2*Dm,
             MD, 0, 0, 0, -(long long)Mrows*2*Dm, 0, 2, 1, in_b + Dm, 1, 1.f, 0, nullptr, 2);
        gemm(128, iwh + 2*Dm*Dm, iwl + 2*Dm*Dm, kvh, kvl, nullptr, P.vth + Mrows, P.vtl + Mrows,
             Dm, Mrows, Dm, Dm, Dm, M2,
             0, 0, MD, 0, -(long long)Mrows, 0, 2, 1, in_b + 2*Dm, 2, 1.f, 0, nullptr, 2);
    }
    fused_attn<<<dim3(4, 2*Bsz*Hh), 256, FA_SMEM()>>>(
        P.qkh, P.qkl, P.vth, P.vtl, P.oh, P.ol);
    gemm(128, P.oh, P.ol, owh, owl, target, nullptr, nullptr,
         M2, Dm, Dm, Dm, Dm, Dm, 0,0,0,0,0,0, 1,1, out_b, 1, 1.f, 0, target, 1);
}

extern "C" void kernel_launch(void* const* d_in, const int* in_sizes, int n_in,
                              void* d_out, int out_size)
{
    const float* x1i     = (const float*)d_in[0];
    const float* x2i     = (const float*)d_in[1];
    const float* proj_w  = (const float*)d_in[2];
    const float* proj_b  = (const float*)d_in[3];
    const float* mha_in_w  = (const float*)d_in[4];
    const float* mha_in_b  = (const float*)d_in[5];
    const float* mha_out_w = (const float*)d_in[6];
    const float* mha_out_b = (const float*)d_in[7];
    const float* ca_in_w   = (const float*)d_in[8];
    const float* ca_in_b   = (const float*)d_in[9];
    const float* ca_out_w  = (const float*)d_in[10];
    const float* ca_out_b  = (const float*)d_in[11];
    const float* Wbins   = (const float*)d_in[12];
    const float* agg     = (const float*)d_in[13];
    const float* Lmat    = (const float*)d_in[14];
    const float* biasp   = (const float*)d_in[15];
    const float* smooth  = (const float*)d_in[16];

    cudaFuncSetAttribute(gemm_mma<128>, cudaFuncAttributeMaxDynamicSharedMemorySize,
                         SMEM_TOTAL_BYTES(128));
    cudaFuncSetAttribute(gemm_mma<64>,  cudaFuncAttributeMaxDynamicSharedMemorySize,
                         SMEM_TOTAL_BYTES(64));
    cudaFuncSetAttribute(fused_attn, cudaFuncAttributeMaxDynamicSharedMemorySize,
                         FA_SMEM());

    Ptrs P;
    cudaGetSymbolAddress((void**)&P.xf, g_xf);
    cudaGetSymbolAddress((void**)&P.cmraw, g_cmraw);
    cudaGetSymbolAddress((void**)&P.cm1, g_cm1);   cudaGetSymbolAddress((void**)&P.cs, g_cs);
    cudaGetSymbolAddress((void**)&P.I, g_I);
    cudaGetSymbolAddress((void**)&P.x1ih, g_x1ih); cudaGetSymbolAddress((void**)&P.x1il, g_x1il);
    cudaGetSymbolAddress((void**)&P.x2ih, g_x2ih); cudaGetSymbolAddress((void**)&P.x2il, g_x2il);
    cudaGetSymbolAddress((void**)&P.wph, g_wph);   cudaGetSymbolAddress((void**)&P.wpl, g_wpl);
    cudaGetSymbolAddress((void**)&P.miwh, g_miwh); cudaGetSymbolAddress((void**)&P.miwl, g_miwl);
    cudaGetSymbolAddress((void**)&P.mowh, g_mowh); cudaGetSymbolAddress((void**)&P.mowl, g_mowl);
    cudaGetSymbolAddress((void**)&P.ciwh, g_ciwh); cudaGetSymbolAddress((void**)&P.ciwl, g_ciwl);
    cudaGetSymbolAddress((void**)&P.cowh, g_cowh); cudaGetSymbolAddress((void**)&P.cowl, g_cowl);
    cudaGetSymbolAddress((void**)&P.xh, g_xh);     cudaGetSymbolAddress((void**)&P.xl, g_xl);
    cudaGetSymbolAddress((void**)&P.th, g_th);     cudaGetSymbolAddress((void**)&P.tl, g_tl);
    cudaGetSymbolAddress((void**)&P.qkh, g_qkh);   cudaGetSymbolAddress((void**)&P.qkl, g_qkl);
    cudaGetSymbolAddress((void**)&P.vth, g_vth);   cudaGetSymbolAddress((void**)&P.vtl, g_vtl);
    cudaGetSymbolAddress((void**)&P.oh, g_oh);     cudaGetSymbolAddress((void**)&P.ol, g_ol);
    cudaGetSymbolAddress((void**)&P.wbth, g_wbth); cudaGetSymbolAddress((void**)&P.wbtl, g_wbtl);
    cudaGetSymbolAddress((void**)&P.hh, g_hh);     cudaGetSymbolAddress((void**)&P.hl, g_hl);

    float* out = (float*)d_out;
    float* pp_out = out + (out_size - Bsz);

    const long long MD = (long long)Mrows * Dm;
    const int NXD2 = M2 * Dm;

    // 0. one-time splits
    split_k<<<(Mrows*IDIM/4 + 255)/256, 256>>>(x1i, P.x1ih, P.x1il, Mrows*IDIM/4);
    split_k<<<(Mrows*IDIM/4 + 255)/256, 256>>>(x2i, P.x2ih, P.x2il, Mrows*IDIM/4);
    split_k<<<(Dm*IDIM/4 + 255)/256, 256>>>(proj_w, P.wph, P.wpl, Dm*IDIM/4);
    split_k<<<(3*Dm*Dm/4 + 255)/256, 256>>>(mha_in_w, P.miwh, P.miwl, 3*Dm*Dm/4);
    split_k<<<(Dm*Dm/4 + 255)/256, 256>>>(mha_out_w, P.mowh, P.mowl, Dm*Dm/4);
    split_k<<<(3*Dm*Dm/4 + 255)/256, 256>>>(ca_in_w, P.ciwh, P.ciwl, 3*Dm*Dm/4);
    split_k<<<(Dm*Dm/4 + 255)/256, 256>>>(ca_out_w, P.cowh, P.cowl, Dm*Dm/4);
    {
        dim3 g(HALFc/32, Dm/32, NBINS);
        transpose_split_k<<<g, dim3(32,8)>>>(Wbins, P.wbth, P.wbtl);
    }

    // 1. input projections
    gemm(128, P.x1ih, P.x1il, P.wph, P.wpl, P.xf, P.xh, P.xl,
         Mrows, Dm, IDIM, IDIM, IDIM, Dm, 0,0,0,0,0,0, 1,1, proj_b, 1, 1.f, 0, nullptr, 3);
    gemm(128, P.x2ih, P.x2il, P.wph, P.wpl, P.xf + MD, P.xh + MD, P.xl + MD,
         Mrows, Dm, IDIM, IDIM, IDIM, Dm, 0,0,0,0,0,0, 1,1, proj_b, 1, 1.f, 0, nullptr, 3);

    // 2. self-attention (+residual)
    run_mha(P, P.xh, P.xl, P.xh, P.xl, P.miwh, P.miwl, mha_in_b,
            P.mowh, P.mowl, mha_out_b, P.xf, false);

    // 3. tanh -> planes
    tanh_split_k<<<(NXD2/4 + 255)/256, 256>>>(P.xf, P.th, P.tl, NXD2/4);

    // 4. cross-attention (+residual), swapped KV
    run_mha(P, P.th, P.tl, P.th, P.tl, P.ciwh, P.ciwl, ca_in_b,
            P.cowh, P.cowl, ca_out_b, P.xf, true);

    // 5. tanh -> planes
    tanh_split_k<<<(NXD2/4 + 255)/256, 256>>>(P.xf, P.th, P.tl, NXD2/4);

    // 6. h = tanh(x @ Wbins)
    gemm(128, P.th, P.tl, P.wbth, P.wbtl, nullptr, P.hh, P.hl,
         Lsz, HALFc, Dm, Dm, Dm, HALFc,
         (long long)Lsz*Dm, 0, 0, (long long)HALFc*Dm,
         (long long)NBINS*Lsz*HALFc, (long long)Lsz*HALFc, 2*Bsz, NBINS,
         nullptr, 0, 1.f, 1, nullptr, 2);

    // 7. cm_raw = h1 h2^T (batch 200, single launch)
    {
        const long long hhalf = (long long)Bsz*NBINS*Lsz*HALFc;
        gemm(128, P.hh, P.hl, P.hh + hhalf, P.hl + hhalf, P.cmraw, nullptr, nullptr,
             Lsz, Lsz, HALFc, HALFc, HALFc, Lsz,
             (long long)Lsz*HALFc, 0, (long long)Lsz*HALFc, 0,
             (long long)Lsz*Lsz, 0, Bsz*NBINS, 1,
             nullptr, 0, 1.f, 0, nullptr, 1);
    }

    // 8. smoothing -> cm + cm1 (single pass)
    {
        int tot4 = Bsz * Lsz * Lsz / 4;
        smooth_k4<<<(tot4 + 255) / 256, 256>>>(P.cmraw, smooth, agg, out, P.cm1);
    }

    // 9. integral image
    colsum_k<<<(Bsz*Lsz + 255) / 256, 256>>>(P.cm1, P.cs);
    rowsum_k<<<(Bsz*Lsz + 255) / 256, 256>>>(P.cs, P.I);

    // 10. head
    finalize_k<<<Bsz, 128>>>(P.I, Lmat, biasp, pp_out);
}

// round 16
// speedup vs baseline: 1.0408x; 1.0178x over previous
#include <cuda_runtime.h>
#include <cuda_bf16.h>
#include <math.h>
#include <stdint.h>

#define Bsz 8
#define Lsz 512
#define IDIM 1024
#define Dm 512
#define Hh 8
#define DH 64
#define NBINS 25
#define PWc 10
#define HALFc 256
#define ISZ 513

#define Mrows (Bsz*Lsz)          // 4096
#define M2 (2*Mrows)             // 8192 combined

typedef __nv_bfloat16 bf16;

// ------------------------- fp32 scratch -------------------------
__device__ float g_xf [(size_t)M2*Dm];
__device__ float g_cmraw[(size_t)Bsz*NBINS*Lsz*Lsz];
__device__ float g_cm1[Bsz*Lsz*Lsz];
__device__ float g_cs [Bsz*Lsz*Lsz];
__device__ float g_I  [Bsz*ISZ*ISZ];

// ------------------------- bf16 hi/lo planes -------------------------
__device__ bf16 g_x1ih[Mrows*IDIM], g_x1il[Mrows*IDIM];
__device__ bf16 g_x2ih[Mrows*IDIM], g_x2il[Mrows*IDIM];
__device__ bf16 g_wph[Dm*IDIM],  g_wpl[Dm*IDIM];
__device__ bf16 g_miwh[3*Dm*Dm], g_miwl[3*Dm*Dm];
__device__ bf16 g_mowh[Dm*Dm],   g_mowl[Dm*Dm];
__device__ bf16 g_ciwh[3*Dm*Dm], g_ciwl[3*Dm*Dm];
__device__ bf16 g_cowh[Dm*Dm],   g_cowl[Dm*Dm];
__device__ bf16 g_xh[(size_t)M2*Dm], g_xl[(size_t)M2*Dm];
__device__ bf16 g_th[(size_t)M2*Dm], g_tl[(size_t)M2*Dm];
__device__ bf16 g_qkh[(size_t)M2*2*Dm], g_qkl[(size_t)M2*2*Dm];   // Q | K combined
__device__ bf16 g_vth[(size_t)Dm*M2], g_vtl[(size_t)Dm*M2];
__device__ bf16 g_oh[(size_t)M2*Dm], g_ol[(size_t)M2*Dm];
__device__ bf16 g_wbth[NBINS*HALFc*Dm], g_wbtl[NBINS*HALFc*Dm];
__device__ bf16 g_hh[(size_t)2*Bsz*NBINS*Lsz*HALFc];
__device__ bf16 g_hl[(size_t)2*Bsz*NBINS*Lsz*HALFc];

// ------------------------- helpers -------------------------
__device__ __forceinline__ uint32_t smem_u32(const void* p){
    uint32_t a;
    asm("{ .reg .u64 t; cvta.to.shared.u64 t, %1; cvt.u32.u64 %0, t; }" : "=r"(a) : "l"(p));
    return a;
}
__device__ __forceinline__ void cp16(uint32_t dst, const void* src){
    asm volatile("cp.async.cg.shared.global [%0], [%1], 16;" :: "r"(dst), "l"(src));
}
#define CP_COMMIT() asm volatile("cp.async.commit_group;" ::: "memory")
#define CP_WAIT(n)  asm volatile("cp.async.wait_group %0;" :: "n"(n) : "memory")

__device__ __forceinline__ uint4 ldm4(uint32_t addr){
    uint4 r;
    asm volatile("ldmatrix.sync.aligned.m8n8.x4.shared.b16 {%0,%1,%2,%3}, [%4];"
        : "=r"(r.x), "=r"(r.y), "=r"(r.z), "=r"(r.w) : "r"(addr));
    return r;
}
__device__ __forceinline__ void mma_bf16(float c[4], uint4 a, uint32_t b0, uint32_t b1){
    asm volatile("mma.sync.aligned.m16n8k16.row.col.f32.bf16.bf16.f32 "
        "{%0,%1,%2,%3}, {%4,%5,%6,%7}, {%8,%9}, {%0,%1,%2,%3};"
        : "+f"(c[0]), "+f"(c[1]), "+f"(c[2]), "+f"(c[3])
        : "r"(a.x), "r"(a.y), "r"(a.z), "r"(a.w), "r"(b0), "r"(b1));
}

// fp32 -> bf16 hi (truncate) / lo (rn of remainder)
__device__ __forceinline__ void cvt_hilo(float4 v, uint2& hi, uint2& lo){
    uint32_t ux = __float_as_uint(v.x), uy = __float_as_uint(v.y),
             uz = __float_as_uint(v.z), uw = __float_as_uint(v.w);
    float hx = __uint_as_float(ux & 0xffff0000u);
    float hy = __uint_as_float(uy & 0xffff0000u);
    float hz = __uint_as_float(uz & 0xffff0000u);
    float hw = __uint_as_float(uw & 0xffff0000u);
    asm("prmt.b32 %0, %1, %2, 0x7632;" : "=r"(hi.x) : "r"(ux), "r"(uy));
    asm("prmt.b32 %0, %1, %2, 0x7632;" : "=r"(hi.y) : "r"(uz), "r"(uw));
    float lx = v.x - hx, ly = v.y - hy, lz = v.z - hz, lw = v.w - hw;
    asm("cvt.rn.bf16x2.f32 %0, %1, %2;" : "=r"(lo.x) : "f"(ly), "f"(lx));
    asm("cvt.rn.bf16x2.f32 %0, %1, %2;" : "=r"(lo.y) : "f"(lw), "f"(lz));
}
__device__ __forceinline__ void cvt_hilo2(float v0, float v1, uint32_t& h, uint32_t& l){
    uint32_t u0 = __float_as_uint(v0), u1 = __float_as_uint(v1);
    asm("prmt.b32 %0, %1, %2, 0x7632;" : "=r"(h) : "r"(u0), "r"(u1));
    float h0 = __uint_as_float(u0 & 0xffff0000u);
    float h1 = __uint_as_float(u1 & 0xffff0000u);
    asm("cvt.rn.bf16x2.f32 %0, %1, %2;" : "=r"(l) : "f"(v1-h1), "f"(v0-h0));
}
__device__ __forceinline__ void split1(float x, bf16* h, bf16* l){
    uint32_t ux = __float_as_uint(x);
    __nv_bfloat16_raw r; r.x = (unsigned short)(ux >> 16);
    *h = r;
    float hf = __uint_as_float(ux & 0xffff0000u);
    *l = __float2bfloat16(x - hf);
}

// ------------------------- mma.sync GEMM -------------------------
template<int BN>
__global__ void __launch_bounds__(256, 2)
gemm_mma(const bf16* __restrict__ Ah, const bf16* __restrict__ Al,
         const bf16* __restrict__ Bh, const bf16* __restrict__ Bl,
         float* __restrict__ C, bf16* __restrict__ Ch, bf16* __restrict__ Cl,
         int K, int lda, int ldb, int ldc,
         long long sA1, long long sA2, long long sB1, long long sB2,
         long long sC1, long long sC2, int batch2,
         const float* __restrict__ bias, int biasMode, float alpha, int act,
         const float* __restrict__ Cres, int outMode)
{
    constexpr int BM = 128, BK = 32;
    constexpr int ROWB = BK*2 + 16;
    constexpr int APL = BM * ROWB;
    constexpr int BPL = BN * ROWB;
    constexpr int STAGE = 2*APL + 2*BPL;
    constexpr int WN = BN / 2;
    constexpr int NB = WN / 8;
    constexpr int KCH = BK / 8;
    constexpr int NCHUNK = (2*BM + 2*BN) * KCH;

    extern __shared__ __align__(128) char smem[];
    const uint32_t sb = smem_u32(smem);

    const int z = blockIdx.z, z1 = z / batch2, z2 = z % batch2;
    const long long aoff = z1*sA1 + z2*sA2;
    const long long boff = z1*sB1 + z2*sB2;
    const long long coff = z1*sC1 + z2*sC2;
    Ah += aoff; Al += aoff;
    Bh += boff; Bl += boff;

    const int m0 = blockIdx.y * BM;
    const int n0 = blockIdx.x * BN;
    const int tid = threadIdx.x;
    const int wid = tid >> 5, lane = tid & 31;
    const int wm = wid >> 1, wn = wid & 1;
    const int mbase = wm * 32;
    const int nbase = wn * WN;

    float acc[2][NB][4];
    #pragma unroll
    for (int i = 0; i < 2; i++)
        #pragma unroll
        for (int j = 0; j < NB; j++)
            #pragma unroll
            for (int u = 0; u < 4; u++) acc[i][j][u] = 0.f;

    const int NC = K / BK;

    auto stage_copy = [&](int c, int s){
        const uint32_t st = sb + (uint32_t)s * STAGE;
        #pragma unroll
        for (int i = 0; i < NCHUNK/256; i++) {
            int idx = tid + i*256;
            const bf16* src; uint32_t dst;
            if (idx < 2*BM*KCH) {
                int p = idx / (BM*KCH); int rem = idx - p*BM*KCH;
                int r = rem >> 2, cc = rem & 3;
                src = (p ? Al : Ah) + (long long)(m0+r)*lda + c*BK + cc*8;
                dst = st + p*APL + r*ROWB + cc*16;
            } else {
                int j = idx - 2*BM*KCH;
                int p = j / (BN*KCH); int rem = j - p*BN*KCH;
                int r = rem >> 2, cc = rem & 3;
                src = (p ? Bl : Bh) + (long long)(n0+r)*ldb + c*BK + cc*8;
                dst = st + 2*APL + p*BPL + r*ROWB + cc*16;
            }
            cp16(dst, src);
        }
    };

    auto compute = [&](int s){
        const uint32_t st = sb + (uint32_t)s * STAGE;
        const uint32_t ab = st;
        const uint32_t bb = st + 2*APL;
        const int arow = mbase + (lane & 15);
        const int akoff = ((lane >> 4) & 1) * 16;
        const int brow0 = nbase + (lane & 7) + ((lane >> 4) & 1) * 8;
        const int bkoff = ((lane >> 3) & 1) * 16;
        #pragma unroll
        for (int ks = 0; ks < BK/16; ks++) {
            const int kb = ks * 32;
            uint4 a[2][2];
            #pragma unroll
            for (int p = 0; p < 2; p++)
                #pragma unroll
                for (int mb = 0; mb < 2; mb++)
                    a[p][mb] = ldm4(ab + p*APL + (arow + mb*16)*ROWB + kb + akoff);
            #pragma unroll
            for (int nb2 = 0; nb2 < NB/2; nb2++) {
                uint4 b0 = ldm4(bb + (brow0 + nb2*16)*ROWB + kb + bkoff);
                uint4 b1 = ldm4(bb + BPL + (brow0 + nb2*16)*ROWB + kb + bkoff);
                #pragma unroll
                for (int mb = 0; mb < 2; mb++) {
                    float* c0 = acc[mb][2*nb2];
                    float* c1 = acc[mb][2*nb2+1];
                    mma_bf16(c0, a[0][mb], b0.x, b0.y);
                    mma_bf16(c1, a[0][mb], b0.z, b0.w);
                    mma_bf16(c0, a[0][mb], b1.x, b1.y);
                    mma_bf16(c1, a[0][mb], b1.z, b1.w);
                    mma_bf16(c0, a[1][mb], b0.x, b0.y);
                    mma_bf16(c1, a[1][mb], b0.z, b0.w);
                }
            }
        }
    };

    stage_copy(0, 0);
    CP_COMMIT();
    for (int c = 0; c < NC; c++) {
        CP_WAIT(0);
        __syncthreads();
        if (c + 1 < NC) { stage_copy(c + 1, (c + 1) & 1); CP_COMMIT(); }
        compute(c & 1);
    }

    const int g = lane >> 2, t = lane & 3;
    #pragma unroll
    for (int mb = 0; mb < 2; mb++) {
        #pragma unroll
        for (int half = 0; half < 2; half++) {
            const int row = m0 + mbase + mb*16 + g + half*8;
            const long long rowo = coff + (long long)row * ldc;
            float brow = (biasMode == 2) ? bias[row] : 0.f;
            #pragma unroll
            for (int nb = 0; nb < NB; nb++) {
                const int col = n0 + nbase + nb*8 + 2*t;
                float v0 = acc[mb][nb][half*2+0] * alpha;
                float v1 = acc[mb][nb][half*2+1] * alpha;
                if (biasMode == 1) {
                    float2 bb = *reinterpret_cast<const float2*>(&bias[col]);
                    v0 += bb.x; v1 += bb.y;
                } else if (biasMode == 2) {
                    v0 += brow; v1 += brow;
                }
                if (Cres) {
                    float2 rr = *reinterpret_cast<const float2*>(&Cres[rowo + col]);
                    v0 += rr.x; v1 += rr.y;
                }
                if (act) { v0 = tanhf(v0); v1 = tanhf(v1); }
                if (outMode & 1)
                    *reinterpret_cast<float2*>(&C[rowo + col]) = make_float2(v0, v1);
                if (outMode & 2) {
                    uint32_t h, l;
                    cvt_hilo2(v0, v1, h, l);
                    *reinterpret_cast<uint32_t*>(&Ch[rowo + col]) = h;
                    *reinterpret_cast<uint32_t*>(&Cl[rowo + col]) = l;
                }
            }
        }
    }
}

// ------------------------- fused attention (double-buffered K/V) -------------------------
__global__ void __launch_bounds__(256, 1)
fused_attn(const bf16* __restrict__ QKh, const bf16* __restrict__ QKl,
           const bf16* __restrict__ Vth, const bf16* __restrict__ Vtl,
           bf16* __restrict__ Oh, bf16* __restrict__ Ol)
{
    constexpr int LDQ = 2*Dm;
    constexpr int QROWB = 144;
    constexpr int KROWB = 144;
    constexpr int VROWB = 272;
    constexpr int QPL = 128 * QROWB;         // 18432
    constexpr int KPL = 128 * KROWB;         // 18432
    constexpr int VPL = 64 * VROWB;          // 17408
    constexpr int KST = 2 * KPL;             // one K stage (both planes)
    constexpr int VST = 2 * VPL;             // one V stage

    extern __shared__ __align__(128) char smem[];
    const uint32_t sbm = smem_u32(smem);
    const uint32_t qb = sbm;
    const uint32_t kB = qb + 2*QPL;
    const uint32_t vB = kB + 2*KST;
    float* maxred = reinterpret_cast<float*>(smem + 2*QPL + 2*KST + 2*VST);
    float* sumred = maxred + 256;
    float* oex    = sumred + 256;

    const int tid = threadIdx.x;
    const int wid = tid >> 5, lane = tid & 31;
    const int wm = wid >> 1, wn = wid & 1;
    const int g = lane >> 2, t = lane & 3;

    const int sbatch = blockIdx.y >> 3;
    const int h = blockIdx.y & 7;
    const long long tb = (long long)sbatch * Lsz;
    const int q0 = blockIdx.x * 128;

    #pragma unroll
    for (int i = 0; i < 8; i++) {
        int idx = tid + i*256;
        int p = idx >> 10, rem = idx & 1023;
        int r = rem >> 3, cc = rem & 7;
        const bf16* src = (p ? QKl : QKh) + (tb + q0 + r)*LDQ + h*DH + cc*8;
        cp16(qb + p*QPL + r*QROWB + cc*16, src);
    }

    auto stage_kv = [&](int kt, int s){
        #pragma unroll
        for (int i = 0; i < 8; i++) {
            int idx = tid + i*256;
            int p = idx >> 10, rem = idx & 1023;
            int r = rem >> 3, cc = rem & 7;
            const bf16* src = (p ? QKl : QKh) + (tb + kt*128 + r)*LDQ + Dm + h*DH + cc*8;
            cp16(kB + (uint32_t)s*KST + p*KPL + r*KROWB + cc*16, src);
        }
        #pragma unroll
        for (int i = 0; i < 8; i++) {
            int idx = tid + i*256;
            int p = idx >> 10, rem = idx & 1023;
            int r = rem >> 4, cc = rem & 15;
            const bf16* src = (p ? Vtl : Vth) + (long long)(h*DH + r)*M2 + tb + kt*128 + cc*8;
            cp16(vB + (uint32_t)s*VST + p*VPL + r*VROWB + cc*16, src);
        }
    };

    float oacc[2][8][4];
    float sacc[2][8][4];
    float mrow[2][2], lrow[2][2];
    #pragma unroll
    for (int mb = 0; mb < 2; mb++) {
        #pragma unroll
        for (int nb = 0; nb < 8; nb++)
            #pragma unroll
            for (int u = 0; u < 4; u++) oacc[mb][nb][u] = 0.f;
        mrow[mb][0] = -1e30f; mrow[mb][1] = -1e30f;
        lrow[mb][0] = 0.f;    lrow[mb][1] = 0.f;
    }

    stage_kv(0, 0);
    CP_COMMIT(); CP_WAIT(0);
    __syncthreads();

    const int arow  = wm*32 + (lane & 15);
    const int akoff = ((lane >> 4) & 1) * 16;
    const int brow0 = wn*64 + (lane & 7) + ((lane >> 4) & 1) * 8;
    const int bkoff = ((lane >> 3) & 1) * 16;
    const int dbrow0 = (lane & 7) + ((lane >> 4) & 1) * 8;

    for (int kt = 0; kt < 4; kt++) {
        const int s = kt & 1;
        const uint32_t kbb = kB + (uint32_t)s*KST;
        const uint32_t vb  = vB + (uint32_t)s*VST;
        // ---- S = Q K^T ----
        #pragma unroll
        for (int mb = 0; mb < 2; mb++)
            #pragma unroll
            for (int nb = 0; nb < 8; nb++)
                #pragma unroll
                for (int u = 0; u < 4; u++) sacc[mb][nb][u] = 0.f;
        #pragma unroll
        for (int ks = 0; ks < 4; ks++) {
            const int kb2 = ks * 32;
            uint4 a[2][2];
            #pragma unroll
            for (int p = 0; p < 2; p++)
                #pragma unroll
                for (int mb = 0; mb < 2; mb++)
                    a[p][mb] = ldm4(qb + p*QPL + (arow + mb*16)*QROWB + kb2 + akoff);
            #pragma unroll
            for (int nb2 = 0; nb2 < 4; nb2++) {
                uint4 b0 = ldm4(kbb + (brow0 + nb2*16)*KROWB + kb2 + bkoff);
                uint4 b1 = ldm4(kbb + KPL + (brow0 + nb2*16)*KROWB + kb2 + bkoff);
                #pragma unroll
                for (int mb = 0; mb < 2; mb++) {
                    float* c0 = sacc[mb][2*nb2];
                    float* c1 = sacc[mb][2*nb2+1];
                    mma_bf16(c0, a[0][mb], b0.x, b0.y);
                    mma_bf16(c1, a[0][mb], b0.z, b0.w);
                    mma_bf16(c0, a[0][mb], b1.x, b1.y);
                    mma_bf16(c1, a[0][mb], b1.z, b1.w);
                    mma_bf16(c0, a[1][mb], b0.x, b0.y);
                    mma_bf16(c1, a[1][mb], b0.z, b0.w);
                }
            }
        }
        // prefetch next K/V tile into the other stage (overlaps softmax+PV)
        if (kt < 3) { stage_kv(kt + 1, s ^ 1); CP_COMMIT(); }
        // ---- scale + online softmax ----
        #pragma unroll
        for (int mb = 0; mb < 2; mb++)
            #pragma unroll
            for (int nb = 0; nb < 8; nb++)
                #pragma unroll
                for (int u = 0; u < 4; u++) sacc[mb][nb][u] *= 0.125f;
        #pragma unroll
        for (int mb = 0; mb < 2; mb++)
            #pragma unroll
            for (int half = 0; half < 2; half++) {
                float mx = -1e30f;
                #pragma unroll
                for (int nb = 0; nb < 8; nb++) {
                    mx = fmaxf(mx, sacc[mb][nb][half*2]);
                    mx = fmaxf(mx, sacc[mb][nb][half*2+1]);
                }
                mx = fmaxf(mx, __shfl_xor_sync(0xffffffffu, mx, 1));
                mx = fmaxf(mx, __shfl_xor_sync(0xffffffffu, mx, 2));
                if (t == 0) maxred[wn*128 + wm*32 + mb*16 + g + half*8] = mx;
            }
        __syncthreads();
        #pragma unroll
        for (int mb = 0; mb < 2; mb++)
            #pragma unroll
            for (int half = 0; half < 2; half++) {
                const int r = wm*32 + mb*16 + g + half*8;
                float mt = fmaxf(maxred[r], maxred[128 + r]);
                float mnew = fmaxf(mrow[mb][half], mt);
                float corr = expf(mrow[mb][half] - mnew);
                mrow[mb][half] = mnew;
                lrow[mb][half] *= corr;
                float sum = 0.f;
                #pragma unroll
                for (int nb = 0; nb < 8; nb++) {
                    float p0 = expf(sacc[mb][nb][half*2]   - mnew);
                    float p1 = expf(sacc[mb][nb][half*2+1] - mnew);
                    sacc[mb][nb][half*2]   = p0;
                    sacc[mb][nb][half*2+1] = p1;
                    sum += p0 + p1;
                    oacc[mb][nb][half*2]   *= corr;
                    oacc[mb][nb][half*2+1] *= corr;
                }
                sum += __shfl_xor_sync(0xffffffffu, sum, 1);
                sum += __shfl_xor_sync(0xffffffffu, sum, 2);
                if (t == 0) sumred[wn*128 + r] = sum;
            }
        __syncthreads();
        #pragma unroll
        for (int mb = 0; mb < 2; mb++)
            #pragma unroll
            for (int half = 0; half < 2; half++) {
                const int r = wm*32 + mb*16 + g + half*8;
                lrow[mb][half] += sumred[r] + sumred[128 + r];
            }
        // ---- P V ----
        #pragma unroll
        for (int ksp = 0; ksp < 4; ksp++) {
            uint4 pah[2], pal[2];
            #pragma unroll
            for (int mb = 0; mb < 2; mb++) {
                float* b0p = sacc[mb][2*ksp];
                float* b1p = sacc[mb][2*ksp+1];
                cvt_hilo2(b0p[0], b0p[1], pah[mb].x, pal[mb].x);
                cvt_hilo2(b0p[2], b0p[3], pah[mb].y, pal[mb].y);
                cvt_hilo2(b1p[0], b1p[1], pah[mb].z, pal[mb].z);
                cvt_hilo2(b1p[2], b1p[3], pah[mb].w, pal[mb].w);
            }
            const int vcol = (wn*64 + ksp*16)*2 + bkoff;
            #pragma unroll
            for (int nb2 = 0; nb2 < 4; nb2++) {
                uint4 bh = ldm4(vb + (dbrow0 + nb2*16)*VROWB + vcol);
                uint4 bl = ldm4(vb + VPL + (dbrow0 + nb2*16)*VROWB + vcol);
                #pragma unroll
                for (int mb = 0; mb < 2; mb++) {
                    float* c0 = oacc[mb][2*nb2];
                    float* c1 = oacc[mb][2*nb2+1];
                    mma_bf16(c0, pah[mb], bh.x, bh.y);
                    mma_bf16(c1, pah[mb], bh.z, bh.w);
                    mma_bf16(c0, pah[mb], bl.x, bl.y);
                    mma_bf16(c1, pah[mb], bl.z, bl.w);
                    mma_bf16(c0, pal[mb], bh.x, bh.y);
                    mma_bf16(c1, pal[mb], bh.z, bh.w);
                }
            }
        }
        if (kt < 3) {
            CP_WAIT(0);
            __syncthreads();
        }
    }

    // ---- combine wn partials, normalize, write planes ----
    if (wn == 1) {
        #pragma unroll
        for (int mb = 0; mb < 2; mb++)
            #pragma unroll
            for (int half = 0; half < 2; half++) {
                const int r = wm*32 + mb*16 + g + half*8;
                #pragma unroll
                for (int nb = 0; nb < 8; nb++) {
                    oex[r*64 + nb*8 + 2*t]     = oacc[mb][nb][half*2];
                    oex[r*64 + nb*8 + 2*t + 1] = oacc[mb][nb][half*2+1];
                }
            }
    }
    __syncthreads();
    if (wn == 0) {
        #pragma unroll
        for (int mb = 0; mb < 2; mb++)
            #pragma unroll
            for (int half = 0; half < 2; half++) {
                const int r = wm*32 + mb*16 + g + half*8;
                const float inv = 1.f / lrow[mb][half];
                const long long rowo = (tb + q0 + r)*Dm + h*DH;
                #pragma unroll
                for (int nb = 0; nb < 8; nb++) {
                    const int col = nb*8 + 2*t;
                    float v0 = (oacc[mb][nb][half*2]   + oex[r*64 + col])     * inv;
                    float v1 = (oacc[mb][nb][half*2+1] + oex[r*64 + col + 1]) * inv;
                    uint32_t hh, ll;
                    cvt_hilo2(v0, v1, hh, ll);
                    *reinterpret_cast<uint32_t*>(&Oh[rowo + col]) = hh;
                    *reinterpret_cast<uint32_t*>(&Ol[rowo + col]) = ll;
                }
            }
    }
}

// ------------------------- one-shot split of inputs + all weights -------------------------
// Segments (float4 units, compile-time): x1, x2, proj_w, mha_in_w, mha_out_w, ca_in_w, ca_out_w
#define SEG_X   (Mrows*IDIM/4)        // 1048576
#define SEG_PW  (Dm*IDIM/4)           // 131072
#define SEG_IW  (3*Dm*Dm/4)           // 196608
#define SEG_OW  (Dm*Dm/4)             // 65536
#define CUM1 (SEG_X)
#define CUM2 (2*SEG_X)
#define CUM3 (CUM2 + SEG_PW)
#define CUM4 (CUM3 + SEG_IW)
#define CUM5 (CUM4 + SEG_OW)
#define CUM6 (CUM5 + SEG_IW)
#define CUM7 (CUM6 + SEG_OW)          // 2752512 total

__global__ void __launch_bounds__(256)
split_all(const float* __restrict__ x1, const float* __restrict__ x2,
          const float* __restrict__ pw, const float* __restrict__ miw,
          const float* __restrict__ mow, const float* __restrict__ ciw,
          const float* __restrict__ cow,
          bf16* x1h, bf16* x1l, bf16* x2h, bf16* x2l,
          bf16* pwh, bf16* pwl, bf16* miwh, bf16* miwl,
          bf16* mowh, bf16* mowl, bf16* ciwh, bf16* ciwl,
          bf16* cowh, bf16* cowl)
{
    int i = blockIdx.x * blockDim.x + threadIdx.x;
    if (i >= CUM7) return;
    const float* in; bf16 *oh, *ol; int base;
    if      (i < CUM1) { in = x1;  oh = x1h;  ol = x1l;  base = 0;    }
    else if (i < CUM2) { in = x2;  oh = x2h;  ol = x2l;  base = CUM1; }
    else if (i < CUM3) { in = pw;  oh = pwh;  ol = pwl;  base = CUM2; }
    else if (i < CUM4) { in = miw; oh = miwh; ol = miwl; base = CUM3; }
    else if (i < CUM5) { in = mow; oh = mowh; ol = mowl; base = CUM4; }
    else if (i < CUM6) { in = ciw; oh = ciwh; ol = ciwl; base = CUM5; }
    else               { in = cow; oh = cowh; ol = cowl; base = CUM6; }
    int j = i - base;
    float4 v = reinterpret_cast<const float4*>(in)[j];
    uint2 h, l; cvt_hilo(v, h, l);
    reinterpret_cast<uint2*>(oh)[j] = h;
    reinterpret_cast<uint2*>(ol)[j] = l;
}

__global__ void tanh_split_k(const float* __restrict__ in, bf16* __restrict__ oh,
                             bf16* __restrict__ ol, int n4)
{
    int i = blockIdx.x * blockDim.x + threadIdx.x;
    if (i >= n4) return;
    float4 v = reinterpret_cast<const float4*>(in)[i];
    v.x = tanhf(v.x); v.y = tanhf(v.y); v.z = tanhf(v.z); v.w = tanhf(v.w);
    uint2 h, l; cvt_hilo(v, h, l);
    reinterpret_cast<uint2*>(oh)[i] = h;
    reinterpret_cast<uint2*>(ol)[i] = l;
}
// Wbins (n, d=512, k=256) -> planes (n, k=256, d=512)
__global__ void transpose_split_k(const float* __restrict__ in,
                                  bf16* __restrict__ oh, bf16* __restrict__ ol)
{
    __shared__ float tile[32][33];
    int n = blockIdx.z;
    int k0 = blockIdx.x * 32, d0 = blockIdx.y * 32;
    in += (size_t)n * Dm * HALFc;
    oh += (size_t)n * HALFc * Dm;
    ol += (size_t)n * HALFc * Dm;
    int tx = threadIdx.x, ty = threadIdx.y;
    #pragma unroll
    for (int i = ty; i < 32; i += 8)
        tile[i][tx] = in[(d0 + i) * HALFc + k0 + tx];
    __syncthreads();
    #pragma unroll
    for (int i = ty; i < 32; i += 8) {
        bf16 h, l; split1(tile[tx][i], &h, &l);
        oh[(k0 + i) * Dm + d0 + tx] = h;
        ol[(k0 + i) * Dm + d0 + tx] = l;
    }
}

// ------------------------- bin smoothing + aggregate (float4) -------------------------
__global__ void __launch_bounds__(256)
smooth_k4(const float* __restrict__ raw, const float* __restrict__ sm,
          const float* __restrict__ agg, float* __restrict__ cm_out,
          float* __restrict__ cm1)
{
    const int tot4 = Bsz * Lsz * Lsz / 4;
    int idx = blockIdx.x * blockDim.x + threadIdx.x;
    if (idx >= tot4) return;
    const int PS = Lsz * Lsz / 4;
    int b   = idx / PS;
    int rem = idx % PS;

    const float4* base = reinterpret_cast<const float4*>(raw)
                       + (size_t)b * NBINS * PS + rem;
    float4 rv[NBINS];
    #pragma unroll
    for (int n = 0; n < NBINS; n++) rv[n] = base[(size_t)n * PS];

    float sw[5];
    #pragma unroll
    for (int k = 0; k < 5; k++) sw[k] = sm[k];

    float4* outb = reinterpret_cast<float4*>(cm_out) + (size_t)b * NBINS * PS + rem;
    float4 acc = make_float4(0.f, 0.f, 0.f, 0.f);
    #pragma unroll
    for (int n = 0; n < NBINS; n++) {
        float4 v = make_float4(0.f, 0.f, 0.f, 0.f);
        #pragma unroll
        for (int k = 0; k < 5; k++) {
            int m = n + k - 2;
            if (m >= 0 && m < NBINS) {
                v.x += sw[k] * rv[m].x;
                v.y += sw[k] * rv[m].y;
                v.z += sw[k] * rv[m].z;
                v.w += sw[k] * rv[m].w;
            }
        }
        outb[(size_t)n * PS] = v;
        float a = agg[n];
        acc.x += a * v.x; acc.y += a * v.y;
        acc.z += a * v.z; acc.w += a * v.w;
    }
    float4 o = make_float4(tanhf(acc.x), tanhf(acc.y), tanhf(acc.z), tanhf(acc.w));
    reinterpret_cast<float4*>(cm1)[idx] = o;
}

// ------------------------- integral image + head -------------------------
__global__ void colsum_k(const float* __restrict__ cm1, float* __restrict__ cs)
{
    int t = blockIdx.x * blockDim.x + threadIdx.x;
    if (t >= Bsz * Lsz) return;
    int b = t / Lsz, j = t % Lsz;
    const float* src = cm1 + (long long)b * Lsz * Lsz + j;
    float* dst       = cs  + (long long)b * Lsz * Lsz + j;
    float acc = 0.f;
    for (int i = 0; i < Lsz; i++) {
        acc += src[(long long)i * Lsz];
        dst[(long long)i * Lsz] = acc;
    }
}
__global__ void rowsum_k(const float* __restrict__ cs, float* __restrict__ I)
{
    int t = blockIdx.x * blockDim.x + threadIdx.x;
    if (t >= Bsz * Lsz) return;
    int b = t / Lsz, i = t % Lsz;
    const float* src = cs + (long long)b * Lsz * Lsz + (long long)i * Lsz;
    float* row = I + (long long)b * ISZ * ISZ + (long long)(i + 1) * ISZ;
    float acc = 0.f;
    row[0] = 0.f;
    for (int j = 0; j < Lsz; j++) { acc += src[j]; row[j + 1] = acc; }
    if (i == 0) {
        float* r0 = I + (long long)b * ISZ * ISZ;
        for (int c = 0; c < ISZ; c++) r0[c] = 0.f;
    }
}
__global__ void finalize_k(const float* __restrict__ I, const float* __restrict__ Lmat,
                           const float* __restrict__ biasp, float* __restrict__ pp)
{
    int b = blockIdx.x;
    __shared__ float terms[128];
    int t = threadIdx.x;
    float val = 0.f;
    if (t < PWc * PWc) {
        int p = t / PWc, q = t % PWc;
        const float* Ib = I + (long long)b * ISZ * ISZ;
        const int Hp = Lsz - PWc + 1;
        float w = Ib[(Hp + p) * ISZ + (Hp + q)] - Ib[(Hp + p) * ISZ + q]
                - Ib[p * ISZ + (Hp + q)]       + Ib[p * ISZ + q];
        val = tanhf(w) * Lmat[t];
    }
    terms[t] = val;
    __syncthreads();
    if (t == 0) {
        float s = 0.f;
        for (int i = 0; i < PWc * PWc; i++) s += terms[i];
        pp[b] = 1.0f / (1.0f + expf(-(s + biasp[0])));
    }
}

// ------------------------- host-side -------------------------
static int SMEM_TOTAL_BYTES(int BN) { return 2 * (2*128 + 2*BN) * (32*2 + 16); }
static int FA_SMEM() {
    // Q(2 planes) + K(2 stages x 2 planes) + V(2 stages x 2 planes) + reductions
    return 2*128*144 + 2*(2*128*144) + 2*(2*64*272) + (256 + 256 + 128*64)*4;  // 215040
}

static void gemm(int BN, const bf16* Ah, const bf16* Al, const bf16* Bh, const bf16* Bl,
                 float* C, bf16* Ch, bf16* Cl,
                 int M, int N, int K, int lda, int ldb, int ldc,
                 long long sA1, long long sA2, long long sB1, long long sB2,
                 long long sC1, long long sC2, int batch1, int batch2,
                 const float* bias, int biasMode, float alpha, int act,
                 const float* Cres, int outMode)
{
    dim3 grid(N / BN, M / 128, batch1 * batch2);
    if (BN == 128)
        gemm_mma<128><<<grid, 256, SMEM_TOTAL_BYTES(128)>>>(Ah, Al, Bh, Bl, C, Ch, Cl,
            K, lda, ldb, ldc, sA1, sA2, sB1, sB2, sC1, sC2, batch2,
            bias, biasMode, alpha, act, Cres, outMode);
    else
        gemm_mma<64><<<grid, 256, SMEM_TOTAL_BYTES(64)>>>(Ah, Al, Bh, Bl, C, Ch, Cl,
            K, lda, ldb, ldc, sA1, sA2, sB1, sB2, sC1, sC2, batch2,
            bias, biasMode, alpha, act, Cres, outMode);
}

struct Ptrs {
    float *xf, *cmraw, *cm1, *cs, *I;
    bf16 *x1ih,*x1il,*x2ih,*x2il,*wph,*wpl,*miwh,*miwl,*mowh,*mowl,*ciwh,*ciwl,*cowh,*cowl;
    bf16 *xh,*xl,*th,*tl,*qkh,*qkl,*vth,*vtl,*oh,*ol;
    bf16 *wbth,*wbtl,*hh,*hl;
};

static void run_mha(const Ptrs& P,
                    const bf16* qsh, const bf16* qsl,
                    const bf16* kvh, const bf16* kvl,
                    const bf16* iwh, const bf16* iwl, const float* in_b,
                    const bf16* owh, const bf16* owl, const float* out_b,
                    float* target, bool swapKV)
{
    const long long MD = (long long)Mrows * Dm;
    if (!swapKV) {
        gemm(128, qsh, qsl, iwh, iwl, nullptr, P.qkh, P.qkl,
             M2, 2*Dm, Dm, Dm, Dm, 2*Dm, 0,0,0,0,0,0, 1,1, in_b, 1, 1.f, 0, nullptr, 2);
        gemm(128, iwh + 2*Dm*Dm, iwl + 2*Dm*Dm, kvh, kvl, nullptr, P.vth, P.vtl,
             Dm, M2, Dm, Dm, Dm, M2, 0,0,0,0,0,0, 1,1, in_b + 2*Dm, 2, 1.f, 0, nullptr, 2);
    } else {
        gemm(128, qsh, qsl, iwh, iwl, nullptr, P.qkh, P.qkl,
             M2, Dm, Dm, Dm, Dm, 2*Dm, 0,0,0,0,0,0, 1,1, in_b, 1, 1.f, 0, nullptr, 2);
        gemm(128, kvh, kvl, iwh + Dm*Dm, iwl + Dm*Dm, nullptr,
             P.qkh + Dm + (long long)Mrows*2*Dm, P.qkl + Dm + (long long)Mrows*2*Dm,
             Mrows, Dm, Dm, Dm, Dm, 2*Dm,
             MD, 0, 0, 0, -(long long)Mrows*2*Dm, 0, 2, 1, in_b + Dm, 1, 1.f, 0, nullptr, 2);
        gemm(128, iwh + 2*Dm*Dm, iwl + 2*Dm*Dm, kvh, kvl, nullptr, P.vth + Mrows, P.vtl + Mrows,
             Dm, Mrows, Dm, Dm, Dm, M2,
             0, 0, MD, 0, -(long long)Mrows, 0, 2, 1, in_b + 2*Dm, 2, 1.f, 0, nullptr, 2);
    }
    fused_attn<<<dim3(4, 2*Bsz*Hh), 256, FA_SMEM()>>>(
        P.qkh, P.qkl, P.vth, P.vtl, P.oh, P.ol);
    gemm(128, P.oh, P.ol, owh, owl, target, nullptr, nullptr,
         M2, Dm, Dm, Dm, Dm, Dm, 0,0,0,0,0,0, 1,1, out_b, 1, 1.f, 0, target, 1);
}

extern "C" void kernel_launch(void* const* d_in, const int* in_sizes, int n_in,
                              void* d_out, int out_size)
{
    const float* x1i     = (const float*)d_in[0];
    const float* x2i     = (const float*)d_in[1];
    const float* proj_w  = (const float*)d_in[2];
    const float* proj_b  = (const float*)d_in[3];
    const float* mha_in_w  = (const float*)d_in[4];
    const float* mha_in_b  = (const float*)d_in[5];
    const float* mha_out_w = (const float*)d_in[6];
    const float* mha_out_b = (const float*)d_in[7];
    const float* ca_in_w   = (const float*)d_in[8];
    const float* ca_in_b   = (const float*)d_in[9];
    const float* ca_out_w  = (const float*)d_in[10];
    const float* ca_out_b  = (const float*)d_in[11];
    const float* Wbins   = (const float*)d_in[12];
    const float* agg     = (const float*)d_in[13];
    const float* Lmat    = (const float*)d_in[14];
    const float* biasp   = (const float*)d_in[15];
    const float* smooth  = (const float*)d_in[16];

    cudaFuncSetAttribute(gemm_mma<128>, cudaFuncAttributeMaxDynamicSharedMemorySize,
                         SMEM_TOTAL_BYTES(128));
    cudaFuncSetAttribute(gemm_mma<64>,  cudaFuncAttributeMaxDynamicSharedMemorySize,
                         SMEM_TOTAL_BYTES(64));
    cudaFuncSetAttribute(fused_attn, cudaFuncAttributeMaxDynamicSharedMemorySize,
                         FA_SMEM());

    Ptrs P;
    cudaGetSymbolAddress((void**)&P.xf, g_xf);
    cudaGetSymbolAddress((void**)&P.cmraw, g_cmraw);
    cudaGetSymbolAddress((void**)&P.cm1, g_cm1);   cudaGetSymbolAddress((void**)&P.cs, g_cs);
    cudaGetSymbolAddress((void**)&P.I, g_I);
    cudaGetSymbolAddress((void**)&P.x1ih, g_x1ih); cudaGetSymbolAddress((void**)&P.x1il, g_x1il);
    cudaGetSymbolAddress((void**)&P.x2ih, g_x2ih); cudaGetSymbolAddress((void**)&P.x2il, g_x2il);
    cudaGetSymbolAddress((void**)&P.wph, g_wph);   cudaGetSymbolAddress((void**)&P.wpl, g_wpl);
    cudaGetSymbolAddress((void**)&P.miwh, g_miwh); cudaGetSymbolAddress((void**)&P.miwl, g_miwl);
    cudaGetSymbolAddress((void**)&P.mowh, g_mowh); cudaGetSymbolAddress((void**)&P.mowl, g_mowl);
    cudaGetSymbolAddress((void**)&P.ciwh, g_ciwh); cudaGetSymbolAddress((void**)&P.ciwl, g_ciwl);
    cudaGetSymbolAddress((void**)&P.cowh, g_cowh); cudaGetSymbolAddress((void**)&P.cowl, g_cowl);
    cudaGetSymbolAddress((void**)&P.xh, g_xh);     cudaGetSymbolAddress((void**)&P.xl, g_xl);
    cudaGetSymbolAddress((void**)&P.th, g_th);     cudaGetSymbolAddress((void**)&P.tl, g_tl);
    cudaGetSymbolAddress((void**)&P.qkh, g_qkh);   cudaGetSymbolAddress((void**)&P.qkl, g_qkl);
    cudaGetSymbolAddress((void**)&P.vth, g_vth);   cudaGetSymbolAddress((void**)&P.vtl, g_vtl);
    cudaGetSymbolAddress((void**)&P.oh, g_oh);     cudaGetSymbolAddress((void**)&P.ol, g_ol);
    cudaGetSymbolAddress((void**)&P.wbth, g_wbth); cudaGetSymbolAddress((void**)&P.wbtl, g_wbtl);
    cudaGetSymbolAddress((void**)&P.hh, g_hh);     cudaGetSymbolAddress((void**)&P.hl, g_hl);

    float* out = (float*)d_out;
    float* pp_out = out + (out_size - Bsz);

    const long long MD = (long long)Mrows * Dm;
    const int NXD2 = M2 * Dm;

    // 0. one-shot splits (inputs + all weights) + Wbins transpose
    split_all<<<(CUM7 + 255)/256, 256>>>(
        x1i, x2i, proj_w, mha_in_w, mha_out_w, ca_in_w, ca_out_w,
        P.x1ih, P.x1il, P.x2ih, P.x2il, P.wph, P.wpl,
        P.miwh, P.miwl, P.mowh, P.mowl, P.ciwh, P.ciwl, P.cowh, P.cowl);
    {
        dim3 g(HALFc/32, Dm/32, NBINS);
        transpose_split_k<<<g, dim3(32,8)>>>(Wbins, P.wbth, P.wbtl);
    }

    // 1. input projections
    gemm(128, P.x1ih, P.x1il, P.wph, P.wpl, P.xf, P.xh, P.xl,
         Mrows, Dm, IDIM, IDIM, IDIM, Dm, 0,0,0,0,0,0, 1,1, proj_b, 1, 1.f, 0, nullptr, 3);
    gemm(128, P.x2ih, P.x2il, P.wph, P.wpl, P.xf + MD, P.xh + MD, P.xl + MD,
         Mrows, Dm, IDIM, IDIM, IDIM, Dm, 0,0,0,0,0,0, 1,1, proj_b, 1, 1.f, 0, nullptr, 3);

    // 2. self-attention (+residual)
    run_mha(P, P.xh, P.xl, P.xh, P.xl, P.miwh, P.miwl, mha_in_b,
            P.mowh, P.mowl, mha_out_b, P.xf, false);

    // 3. tanh -> planes
    tanh_split_k<<<(NXD2/4 + 255)/256, 256>>>(P.xf, P.th, P.tl, NXD2/4);

    // 4. cross-attention (+residual), swapped KV
    run_mha(P, P.th, P.tl, P.th, P.tl, P.ciwh, P.ciwl, ca_in_b,
            P.cowh, P.cowl, ca_out_b, P.xf, true);

    // 5. tanh -> planes
    tanh_split_k<<<(NXD2/4 + 255)/256, 256>>>(P.xf, P.th, P.tl, NXD2/4);

    // 6. h = tanh(x @ Wbins)
    gemm(128, P.th, P.tl, P.wbth, P.wbtl, nullptr, P.hh, P.hl,
         Lsz, HALFc, Dm, Dm, Dm, HALFc,
         (long long)Lsz*Dm, 0, 0, (long long)HALFc*Dm,
         (long long)NBINS*Lsz*HALFc, (long long)Lsz*HALFc, 2*Bsz, NBINS,
         nullptr, 0, 1.f, 1, nullptr, 2);

    // 7. cm_raw = h1 h2^T (batch 200)
    {
        const long long hhalf = (long long)Bsz*NBINS*Lsz*HALFc;
        gemm(128, P.hh, P.hl, P.hh + hhalf, P.hl + hhalf, P.cmraw, nullptr, nullptr,
             Lsz, Lsz, HALFc, HALFc, HALFc, Lsz,
             (long long)Lsz*HALFc, 0, (long long)Lsz*HALFc, 0,
             (long long)Lsz*Lsz, 0, Bsz*NBINS, 1,
             nullptr, 0, 1.f, 0, nullptr, 1);
    }

    // 8. smoothing -> cm + cm1
    {
        int tot4 = Bsz * Lsz * Lsz / 4;
        smooth_k4<<<(tot4 + 255) / 256, 256>>>(P.cmraw, smooth, agg, out, P.cm1);
    }

    // 9. integral image
    colsum_k<<<(Bsz*Lsz + 255) / 256, 256>>>(P.cm1, P.cs);
    rowsum_k<<<(Bsz*Lsz + 255) / 256, 256>>>(P.cs, P.I);

    // 10. head
    finalize_k<<<Bsz, 128>>>(P.I, Lmat, biasp, pp_out);
}

// round 17
// speedup vs baseline: 1.0459x; 1.0050x over previous
#include <cuda_runtime.h>
#include <cuda_bf16.h>
#include <math.h>
#include <stdint.h>

#define Bsz 8
#define Lsz 512
#define IDIM 1024
#define Dm 512
#define Hh 8
#define DH 64
#define NBINS 25
#define PWc 10
#define HALFc 256
#define ISZ 513

#define Mrows (Bsz*Lsz)          // 4096
#define M2 (2*Mrows)             // 8192 combined

typedef __nv_bfloat16 bf16;

// ------------------------- fp32 scratch -------------------------
__device__ float g_xf [(size_t)M2*Dm];
__device__ float g_cmraw[(size_t)Bsz*NBINS*Lsz*Lsz];
__device__ float g_cm1[Bsz*Lsz*Lsz];
__device__ float g_cs [Bsz*Lsz*Lsz];
__device__ float g_I  [Bsz*ISZ*ISZ];

// ------------------------- bf16 hi/lo planes -------------------------
__device__ bf16 g_xih[(size_t)M2*IDIM], g_xil[(size_t)M2*IDIM];   // x1|x2 input planes
__device__ bf16 g_wph[Dm*IDIM],  g_wpl[Dm*IDIM];
__device__ bf16 g_miwh[3*Dm*Dm], g_miwl[3*Dm*Dm];
__device__ bf16 g_mowh[Dm*Dm],   g_mowl[Dm*Dm];
__device__ bf16 g_ciwh[3*Dm*Dm], g_ciwl[3*Dm*Dm];
__device__ bf16 g_cowh[Dm*Dm],   g_cowl[Dm*Dm];
__device__ bf16 g_xh[(size_t)M2*Dm], g_xl[(size_t)M2*Dm];
__device__ bf16 g_th[(size_t)M2*Dm], g_tl[(size_t)M2*Dm];
__device__ bf16 g_qkh[(size_t)M2*2*Dm], g_qkl[(size_t)M2*2*Dm];   // Q | K combined
__device__ bf16 g_vth[(size_t)Dm*M2], g_vtl[(size_t)Dm*M2];
__device__ bf16 g_oh[(size_t)M2*Dm], g_ol[(size_t)M2*Dm];
__device__ bf16 g_wbth[NBINS*HALFc*Dm], g_wbtl[NBINS*HALFc*Dm];
__device__ bf16 g_hh[(size_t)2*Bsz*NBINS*Lsz*HALFc];
__device__ bf16 g_hl[(size_t)2*Bsz*NBINS*Lsz*HALFc];

// ------------------------- helpers -------------------------
__device__ __forceinline__ uint32_t smem_u32(const void* p){
    uint32_t a;
    asm("{ .reg .u64 t; cvta.to.shared.u64 t, %1; cvt.u32.u64 %0, t; }" : "=r"(a) : "l"(p));
    return a;
}
__device__ __forceinline__ void cp16(uint32_t dst, const void* src){
    asm volatile("cp.async.cg.shared.global [%0], [%1], 16;" :: "r"(dst), "l"(src));
}
#define CP_COMMIT() asm volatile("cp.async.commit_group;" ::: "memory")
#define CP_WAIT(n)  asm volatile("cp.async.wait_group %0;" :: "n"(n) : "memory")

__device__ __forceinline__ uint4 ldm4(uint32_t addr){
    uint4 r;
    asm volatile("ldmatrix.sync.aligned.m8n8.x4.shared.b16 {%0,%1,%2,%3}, [%4];"
        : "=r"(r.x), "=r"(r.y), "=r"(r.z), "=r"(r.w) : "r"(addr));
    return r;
}
__device__ __forceinline__ void mma_bf16(float c[4], uint4 a, uint32_t b0, uint32_t b1){
    asm volatile("mma.sync.aligned.m16n8k16.row.col.f32.bf16.bf16.f32 "
        "{%0,%1,%2,%3}, {%4,%5,%6,%7}, {%8,%9}, {%0,%1,%2,%3};"
        : "+f"(c[0]), "+f"(c[1]), "+f"(c[2]), "+f"(c[3])
        : "r"(a.x), "r"(a.y), "r"(a.z), "r"(a.w), "r"(b0), "r"(b1));
}

// fp32 -> bf16 hi (truncate) / lo (rn of remainder)
__device__ __forceinline__ void cvt_hilo(float4 v, uint2& hi, uint2& lo){
    uint32_t ux = __float_as_uint(v.x), uy = __float_as_uint(v.y),
             uz = __float_as_uint(v.z), uw = __float_as_uint(v.w);
    float hx = __uint_as_float(ux & 0xffff0000u);
    float hy = __uint_as_float(uy & 0xffff0000u);
    float hz = __uint_as_float(uz & 0xffff0000u);
    float hw = __uint_as_float(uw & 0xffff0000u);
    asm("prmt.b32 %0, %1, %2, 0x7632;" : "=r"(hi.x) : "r"(ux), "r"(uy));
    asm("prmt.b32 %0, %1, %2, 0x7632;" : "=r"(hi.y) : "r"(uz), "r"(uw));
    float lx = v.x - hx, ly = v.y - hy, lz = v.z - hz, lw = v.w - hw;
    asm("cvt.rn.bf16x2.f32 %0, %1, %2;" : "=r"(lo.x) : "f"(ly), "f"(lx));
    asm("cvt.rn.bf16x2.f32 %0, %1, %2;" : "=r"(lo.y) : "f"(lw), "f"(lz));
}
__device__ __forceinline__ void cvt_hilo2(float v0, float v1, uint32_t& h, uint32_t& l){
    uint32_t u0 = __float_as_uint(v0), u1 = __float_as_uint(v1);
    asm("prmt.b32 %0, %1, %2, 0x7632;" : "=r"(h) : "r"(u0), "r"(u1));
    float h0 = __uint_as_float(u0 & 0xffff0000u);
    float h1 = __uint_as_float(u1 & 0xffff0000u);
    asm("cvt.rn.bf16x2.f32 %0, %1, %2;" : "=r"(l) : "f"(v1-h1), "f"(v0-h0));
}
__device__ __forceinline__ void split1(float x, bf16* h, bf16* l){
    uint32_t ux = __float_as_uint(x);
    __nv_bfloat16_raw r; r.x = (unsigned short)(ux >> 16);
    *h = r;
    float hf = __uint_as_float(ux & 0xffff0000u);
    *l = __float2bfloat16(x - hf);
}

// ------------------------- mma.sync GEMM -------------------------
template<int BN>
__global__ void __launch_bounds__(256, 2)
gemm_mma(const bf16* __restrict__ Ah, const bf16* __restrict__ Al,
         const bf16* __restrict__ Bh, const bf16* __restrict__ Bl,
         float* __restrict__ C, bf16* __restrict__ Ch, bf16* __restrict__ Cl,
         int K, int lda, int ldb, int ldc,
         long long sA1, long long sA2, long long sB1, long long sB2,
         long long sC1, long long sC2, int batch2,
         const float* __restrict__ bias, int biasMode, float alpha, int act,
         const float* __restrict__ Cres, int outMode)
{
    constexpr int BM = 128, BK = 32;
    constexpr int ROWB = BK*2 + 16;
    constexpr int APL = BM * ROWB;
    constexpr int BPL = BN * ROWB;
    constexpr int STAGE = 2*APL + 2*BPL;
    constexpr int WN = BN / 2;
    constexpr int NB = WN / 8;
    constexpr int KCH = BK / 8;
    constexpr int NCHUNK = (2*BM + 2*BN) * KCH;

    extern __shared__ __align__(128) char smem[];
    const uint32_t sb = smem_u32(smem);

    const int z = blockIdx.z, z1 = z / batch2, z2 = z % batch2;
    const long long aoff = z1*sA1 + z2*sA2;
    const long long boff = z1*sB1 + z2*sB2;
    const long long coff = z1*sC1 + z2*sC2;
    Ah += aoff; Al += aoff;
    Bh += boff; Bl += boff;

    const int m0 = blockIdx.y * BM;
    const int n0 = blockIdx.x * BN;
    const int tid = threadIdx.x;
    const int wid = tid >> 5, lane = tid & 31;
    const int wm = wid >> 1, wn = wid & 1;
    const int mbase = wm * 32;
    const int nbase = wn * WN;

    float acc[2][NB][4];
    #pragma unroll
    for (int i = 0; i < 2; i++)
        #pragma unroll
        for (int j = 0; j < NB; j++)
            #pragma unroll
            for (int u = 0; u < 4; u++) acc[i][j][u] = 0.f;

    const int NC = K / BK;

    auto stage_copy = [&](int c, int s){
        const uint32_t st = sb + (uint32_t)s * STAGE;
        #pragma unroll
        for (int i = 0; i < NCHUNK/256; i++) {
            int idx = tid + i*256;
            const bf16* src; uint32_t dst;
            if (idx < 2*BM*KCH) {
                int p = idx / (BM*KCH); int rem = idx - p*BM*KCH;
                int r = rem >> 2, cc = rem & 3;
                src = (p ? Al : Ah) + (long long)(m0+r)*lda + c*BK + cc*8;
                dst = st + p*APL + r*ROWB + cc*16;
            } else {
                int j = idx - 2*BM*KCH;
                int p = j / (BN*KCH); int rem = j - p*BN*KCH;
                int r = rem >> 2, cc = rem & 3;
                src = (p ? Bl : Bh) + (long long)(n0+r)*ldb + c*BK + cc*8;
                dst = st + 2*APL + p*BPL + r*ROWB + cc*16;
            }
            cp16(dst, src);
        }
    };

    auto compute = [&](int s){
        const uint32_t st = sb + (uint32_t)s * STAGE;
        const uint32_t ab = st;
        const uint32_t bb = st + 2*APL;
        const int arow = mbase + (lane & 15);
        const int akoff = ((lane >> 4) & 1) * 16;
        const int brow0 = nbase + (lane & 7) + ((lane >> 4) & 1) * 8;
        const int bkoff = ((lane >> 3) & 1) * 16;
        #pragma unroll
        for (int ks = 0; ks < BK/16; ks++) {
            const int kb = ks * 32;
            uint4 a[2][2];
            #pragma unroll
            for (int p = 0; p < 2; p++)
                #pragma unroll
                for (int mb = 0; mb < 2; mb++)
                    a[p][mb] = ldm4(ab + p*APL + (arow + mb*16)*ROWB + kb + akoff);
            #pragma unroll
            for (int nb2 = 0; nb2 < NB/2; nb2++) {
                uint4 b0 = ldm4(bb + (brow0 + nb2*16)*ROWB + kb + bkoff);
                uint4 b1 = ldm4(bb + BPL + (brow0 + nb2*16)*ROWB + kb + bkoff);
                #pragma unroll
                for (int mb = 0; mb < 2; mb++) {
                    float* c0 = acc[mb][2*nb2];
                    float* c1 = acc[mb][2*nb2+1];
                    mma_bf16(c0, a[0][mb], b0.x, b0.y);
                    mma_bf16(c1, a[0][mb], b0.z, b0.w);
                    mma_bf16(c0, a[0][mb], b1.x, b1.y);
                    mma_bf16(c1, a[0][mb], b1.z, b1.w);
                    mma_bf16(c0, a[1][mb], b0.x, b0.y);
                    mma_bf16(c1, a[1][mb], b0.z, b0.w);
                }
            }
        }
    };

    stage_copy(0, 0);
    CP_COMMIT();
    for (int c = 0; c < NC; c++) {
        CP_WAIT(0);
        __syncthreads();
        if (c + 1 < NC) { stage_copy(c + 1, (c + 1) & 1); CP_COMMIT(); }
        compute(c & 1);
    }

    const int g = lane >> 2, t = lane & 3;
    #pragma unroll
    for (int mb = 0; mb < 2; mb++) {
        #pragma unroll
        for (int half = 0; half < 2; half++) {
            const int row = m0 + mbase + mb*16 + g + half*8;
            const long long rowo = coff + (long long)row * ldc;
            float brow = (biasMode == 2) ? bias[row] : 0.f;
            #pragma unroll
            for (int nb = 0; nb < NB; nb++) {
                const int col = n0 + nbase + nb*8 + 2*t;
                float v0 = acc[mb][nb][half*2+0] * alpha;
                float v1 = acc[mb][nb][half*2+1] * alpha;
                if (biasMode == 1) {
                    float2 bb = *reinterpret_cast<const float2*>(&bias[col]);
                    v0 += bb.x; v1 += bb.y;
                } else if (biasMode == 2) {
                    v0 += brow; v1 += brow;
                }
                if (Cres) {
                    float2 rr = *reinterpret_cast<const float2*>(&Cres[rowo + col]);
                    v0 += rr.x; v1 += rr.y;
                }
                if (act) { v0 = tanhf(v0); v1 = tanhf(v1); }
                if (outMode & 1)
                    *reinterpret_cast<float2*>(&C[rowo + col]) = make_float2(v0, v1);
                if (outMode & 2) {
                    uint32_t h, l;
                    cvt_hilo2(v0, v1, h, l);
                    *reinterpret_cast<uint32_t*>(&Ch[rowo + col]) = h;
                    *reinterpret_cast<uint32_t*>(&Cl[rowo + col]) = l;
                }
            }
        }
    }
}

// ------------------------- fused attention (double-buffered K/V) -------------------------
__global__ void __launch_bounds__(256, 1)
fused_attn(const bf16* __restrict__ QKh, const bf16* __restrict__ QKl,
           const bf16* __restrict__ Vth, const bf16* __restrict__ Vtl,
           bf16* __restrict__ Oh, bf16* __restrict__ Ol)
{
    constexpr int LDQ = 2*Dm;
    constexpr int QROWB = 144;
    constexpr int KROWB = 144;
    constexpr int VROWB = 272;
    constexpr int QPL = 128 * QROWB;
    constexpr int KPL = 128 * KROWB;
    constexpr int VPL = 64 * VROWB;
    constexpr int KST = 2 * KPL;
    constexpr int VST = 2 * VPL;

    extern __shared__ __align__(128) char smem[];
    const uint32_t sbm = smem_u32(smem);
    const uint32_t qb = sbm;
    const uint32_t kB = qb + 2*QPL;
    const uint32_t vB = kB + 2*KST;
    float* maxred = reinterpret_cast<float*>(smem + 2*QPL + 2*KST + 2*VST);
    float* sumred = maxred + 256;
    float* oex    = sumred + 256;

    const int tid = threadIdx.x;
    const int wid = tid >> 5, lane = tid & 31;
    const int wm = wid >> 1, wn = wid & 1;
    const int g = lane >> 2, t = lane & 3;

    const int sbatch = blockIdx.y >> 3;
    const int h = blockIdx.y & 7;
    const long long tb = (long long)sbatch * Lsz;
    const int q0 = blockIdx.x * 128;

    #pragma unroll
    for (int i = 0; i < 8; i++) {
        int idx = tid + i*256;
        int p = idx >> 10, rem = idx & 1023;
        int r = rem >> 3, cc = rem & 7;
        const bf16* src = (p ? QKl : QKh) + (tb + q0 + r)*LDQ + h*DH + cc*8;
        cp16(qb + p*QPL + r*QROWB + cc*16, src);
    }

    auto stage_kv = [&](int kt, int s){
        #pragma unroll
        for (int i = 0; i < 8; i++) {
            int idx = tid + i*256;
            int p = idx >> 10, rem = idx & 1023;
            int r = rem >> 3, cc = rem & 7;
            const bf16* src = (p ? QKl : QKh) + (tb + kt*128 + r)*LDQ + Dm + h*DH + cc*8;
            cp16(kB + (uint32_t)s*KST + p*KPL + r*KROWB + cc*16, src);
        }
        #pragma unroll
        for (int i = 0; i < 8; i++) {
            int idx = tid + i*256;
            int p = idx >> 10, rem = idx & 1023;
            int r = rem >> 4, cc = rem & 15;
            const bf16* src = (p ? Vtl : Vth) + (long long)(h*DH + r)*M2 + tb + kt*128 + cc*8;
            cp16(vB + (uint32_t)s*VST + p*VPL + r*VROWB + cc*16, src);
        }
    };

    float oacc[2][8][4];
    float sacc[2][8][4];
    float mrow[2][2], lrow[2][2];
    #pragma unroll
    for (int mb = 0; mb < 2; mb++) {
        #pragma unroll
        for (int nb = 0; nb < 8; nb++)
            #pragma unroll
            for (int u = 0; u < 4; u++) oacc[mb][nb][u] = 0.f;
        mrow[mb][0] = -1e30f; mrow[mb][1] = -1e30f;
        lrow[mb][0] = 0.f;    lrow[mb][1] = 0.f;
    }

    stage_kv(0, 0);
    CP_COMMIT(); CP_WAIT(0);
    __syncthreads();

    const int arow  = wm*32 + (lane & 15);
    const int akoff = ((lane >> 4) & 1) * 16;
    const int brow0 = wn*64 + (lane & 7) + ((lane >> 4) & 1) * 8;
    const int bkoff = ((lane >> 3) & 1) * 16;
    const int dbrow0 = (lane & 7) + ((lane >> 4) & 1) * 8;

    for (int kt = 0; kt < 4; kt++) {
        const int s = kt & 1;
        const uint32_t kbb = kB + (uint32_t)s*KST;
        const uint32_t vb  = vB + (uint32_t)s*VST;
        #pragma unroll
        for (int mb = 0; mb < 2; mb++)
            #pragma unroll
            for (int nb = 0; nb < 8; nb++)
                #pragma unroll
                for (int u = 0; u < 4; u++) sacc[mb][nb][u] = 0.f;
        #pragma unroll
        for (int ks = 0; ks < 4; ks++) {
            const int kb2 = ks * 32;
            uint4 a[2][2];
            #pragma unroll
            for (int p = 0; p < 2; p++)
                #pragma unroll
                for (int mb = 0; mb < 2; mb++)
                    a[p][mb] = ldm4(qb + p*QPL + (arow + mb*16)*QROWB + kb2 + akoff);
            #pragma unroll
            for (int nb2 = 0; nb2 < 4; nb2++) {
                uint4 b0 = ldm4(kbb + (brow0 + nb2*16)*KROWB + kb2 + bkoff);
                uint4 b1 = ldm4(kbb + KPL + (brow0 + nb2*16)*KROWB + kb2 + bkoff);
                #pragma unroll
                for (int mb = 0; mb < 2; mb++) {
                    float* c0 = sacc[mb][2*nb2];
                    float* c1 = sacc[mb][2*nb2+1];
                    mma_bf16(c0, a[0][mb], b0.x, b0.y);
                    mma_bf16(c1, a[0][mb], b0.z, b0.w);
                    mma_bf16(c0, a[0][mb], b1.x, b1.y);
                    mma_bf16(c1, a[0][mb], b1.z, b1.w);
                    mma_bf16(c0, a[1][mb], b0.x, b0.y);
                    mma_bf16(c1, a[1][mb], b0.z, b0.w);
                }
            }
        }
        if (kt < 3) { stage_kv(kt + 1, s ^ 1); CP_COMMIT(); }
        #pragma unroll
        for (int mb = 0; mb < 2; mb++)
            #pragma unroll
            for (int nb = 0; nb < 8; nb++)
                #pragma unroll
                for (int u = 0; u < 4; u++) sacc[mb][nb][u] *= 0.125f;
        #pragma unroll
        for (int mb = 0; mb < 2; mb++)
            #pragma unroll
            for (int half = 0; half < 2; half++) {
                float mx = -1e30f;
                #pragma unroll
                for (int nb = 0; nb < 8; nb++) {
                    mx = fmaxf(mx, sacc[mb][nb][half*2]);
                    mx = fmaxf(mx, sacc[mb][nb][half*2+1]);
                }
                mx = fmaxf(mx, __shfl_xor_sync(0xffffffffu, mx, 1));
                mx = fmaxf(mx, __shfl_xor_sync(0xffffffffu, mx, 2));
                if (t == 0) maxred[wn*128 + wm*32 + mb*16 + g + half*8] = mx;
            }
        __syncthreads();
        #pragma unroll
        for (int mb = 0; mb < 2; mb++)
            #pragma unroll
            for (int half = 0; half < 2; half++) {
                const int r = wm*32 + mb*16 + g + half*8;
                float mt = fmaxf(maxred[r], maxred[128 + r]);
                float mnew = fmaxf(mrow[mb][half], mt);
                float corr = expf(mrow[mb][half] - mnew);
                mrow[mb][half] = mnew;
                lrow[mb][half] *= corr;
                float sum = 0.f;
                #pragma unroll
                for (int nb = 0; nb < 8; nb++) {
                    float p0 = expf(sacc[mb][nb][half*2]   - mnew);
                    float p1 = expf(sacc[mb][nb][half*2+1] - mnew);
                    sacc[mb][nb][half*2]   = p0;
                    sacc[mb][nb][half*2+1] = p1;
                    sum += p0 + p1;
                    oacc[mb][nb][half*2]   *= corr;
                    oacc[mb][nb][half*2+1] *= corr;
                }
                sum += __shfl_xor_sync(0xffffffffu, sum, 1);
                sum += __shfl_xor_sync(0xffffffffu, sum, 2);
                if (t == 0) sumred[wn*128 + r] = sum;
            }
        __syncthreads();
        #pragma unroll
        for (int mb = 0; mb < 2; mb++)
            #pragma unroll
            for (int half = 0; half < 2; half++) {
                const int r = wm*32 + mb*16 + g + half*8;
                lrow[mb][half] += sumred[r] + sumred[128 + r];
            }
        #pragma unroll
        for (int ksp = 0; ksp < 4; ksp++) {
            uint4 pah[2], pal[2];
            #pragma unroll
            for (int mb = 0; mb < 2; mb++) {
                float* b0p = sacc[mb][2*ksp];
                float* b1p = sacc[mb][2*ksp+1];
                cvt_hilo2(b0p[0], b0p[1], pah[mb].x, pal[mb].x);
                cvt_hilo2(b0p[2], b0p[3], pah[mb].y, pal[mb].y);
                cvt_hilo2(b1p[0], b1p[1], pah[mb].z, pal[mb].z);
                cvt_hilo2(b1p[2], b1p[3], pah[mb].w, pal[mb].w);
            }
            const int vcol = (wn*64 + ksp*16)*2 + bkoff;
            #pragma unroll
            for (int nb2 = 0; nb2 < 4; nb2++) {
                uint4 bh = ldm4(vb + (dbrow0 + nb2*16)*VROWB + vcol);
                uint4 bl = ldm4(vb + VPL + (dbrow0 + nb2*16)*VROWB + vcol);
                #pragma unroll
                for (int mb = 0; mb < 2; mb++) {
                    float* c0 = oacc[mb][2*nb2];
                    float* c1 = oacc[mb][2*nb2+1];
                    mma_bf16(c0, pah[mb], bh.x, bh.y);
                    mma_bf16(c1, pah[mb], bh.z, bh.w);
                    mma_bf16(c0, pah[mb], bl.x, bl.y);
                    mma_bf16(c1, pah[mb], bl.z, bl.w);
                    mma_bf16(c0, pal[mb], bh.x, bh.y);
                    mma_bf16(c1, pal[mb], bh.z, bh.w);
                }
            }
        }
        if (kt < 3) {
            CP_WAIT(0);
            __syncthreads();
        }
    }

    if (wn == 1) {
        #pragma unroll
        for (int mb = 0; mb < 2; mb++)
            #pragma unroll
            for (int half = 0; half < 2; half++) {
                const int r = wm*32 + mb*16 + g + half*8;
                #pragma unroll
                for (int nb = 0; nb < 8; nb++) {
                    oex[r*64 + nb*8 + 2*t]     = oacc[mb][nb][half*2];
                    oex[r*64 + nb*8 + 2*t + 1] = oacc[mb][nb][half*2+1];
                }
            }
    }
    __syncthreads();
    if (wn == 0) {
        #pragma unroll
        for (int mb = 0; mb < 2; mb++)
            #pragma unroll
            for (int half = 0; half < 2; half++) {
                const int r = wm*32 + mb*16 + g + half*8;
                const float inv = 1.f / lrow[mb][half];
                const long long rowo = (tb + q0 + r)*Dm + h*DH;
                #pragma unroll
                for (int nb = 0; nb < 8; nb++) {
                    const int col = nb*8 + 2*t;
                    float v0 = (oacc[mb][nb][half*2]   + oex[r*64 + col])     * inv;
                    float v1 = (oacc[mb][nb][half*2+1] + oex[r*64 + col + 1]) * inv;
                    uint32_t hh, ll;
                    cvt_hilo2(v0, v1, hh, ll);
                    *reinterpret_cast<uint32_t*>(&Oh[rowo + col]) = hh;
                    *reinterpret_cast<uint32_t*>(&Ol[rowo + col]) = ll;
                }
            }
    }
}

// ------------------------- one-shot split of inputs + all weights -------------------------
#define SEG_X   (Mrows*IDIM/4)
#define SEG_PW  (Dm*IDIM/4)
#define SEG_IW  (3*Dm*Dm/4)
#define SEG_OW  (Dm*Dm/4)
#define CUM1 (SEG_X)
#define CUM2 (2*SEG_X)
#define CUM3 (CUM2 + SEG_PW)
#define CUM4 (CUM3 + SEG_IW)
#define CUM5 (CUM4 + SEG_OW)
#define CUM6 (CUM5 + SEG_IW)
#define CUM7 (CUM6 + SEG_OW)

__global__ void __launch_bounds__(256)
split_all(const float* __restrict__ x1, const float* __restrict__ x2,
          const float* __restrict__ pw, const float* __restrict__ miw,
          const float* __restrict__ mow, const float* __restrict__ ciw,
          const float* __restrict__ cow,
          bf16* x1h, bf16* x1l, bf16* x2h, bf16* x2l,
          bf16* pwh, bf16* pwl, bf16* miwh, bf16* miwl,
          bf16* mowh, bf16* mowl, bf16* ciwh, bf16* ciwl,
          bf16* cowh, bf16* cowl)
{
    int i = blockIdx.x * blockDim.x + threadIdx.x;
    if (i >= CUM7) return;
    const float* in; bf16 *oh, *ol; int base;
    if      (i < CUM1) { in = x1;  oh = x1h;  ol = x1l;  base = 0;    }
    else if (i < CUM2) { in = x2;  oh = x2h;  ol = x2l;  base = CUM1; }
    else if (i < CUM3) { in = pw;  oh = pwh;  ol = pwl;  base = CUM2; }
    else if (i < CUM4) { in = miw; oh = miwh; ol = miwl; base = CUM3; }
    else if (i < CUM5) { in = mow; oh = mowh; ol = mowl; base = CUM4; }
    else if (i < CUM6) { in = ciw; oh = ciwh; ol = ciwl; base = CUM5; }
    else               { in = cow; oh = cowh; ol = cowl; base = CUM6; }
    int j = i - base;
    float4 v = reinterpret_cast<const float4*>(in)[j];
    uint2 h, l; cvt_hilo(v, h, l);
    reinterpret_cast<uint2*>(oh)[j] = h;
    reinterpret_cast<uint2*>(ol)[j] = l;
}

__global__ void tanh_split_k(const float* __restrict__ in, bf16* __restrict__ oh,
                             bf16* __restrict__ ol, int n4)
{
    int i = blockIdx.x * blockDim.x + threadIdx.x;
    if (i >= n4) return;
    float4 v = reinterpret_cast<const float4*>(in)[i];
    v.x = tanhf(v.x); v.y = tanhf(v.y); v.z = tanhf(v.z); v.w = tanhf(v.w);
    uint2 h, l; cvt_hilo(v, h, l);
    reinterpret_cast<uint2*>(oh)[i] = h;
    reinterpret_cast<uint2*>(ol)[i] = l;
}
// Wbins (n, d=512, k=256) -> planes (n, k=256, d=512)
__global__ void transpose_split_k(const float* __restrict__ in,
                                  bf16* __restrict__ oh, bf16* __restrict__ ol)
{
    __shared__ float tile[32][33];
    int n = blockIdx.z;
    int k0 = blockIdx.x * 32, d0 = blockIdx.y * 32;
    in += (size_t)n * Dm * HALFc;
    oh += (size_t)n * HALFc * Dm;
    ol += (size_t)n * HALFc * Dm;
    int tx = threadIdx.x, ty = threadIdx.y;
    #pragma unroll
    for (int i = ty; i < 32; i += 8)
        tile[i][tx] = in[(d0 + i) * HALFc + k0 + tx];
    __syncthreads();
    #pragma unroll
    for (int i = ty; i < 32; i += 8) {
        bf16 h, l; split1(tile[tx][i], &h, &l);
        oh[(k0 + i) * Dm + d0 + tx] = h;
        ol[(k0 + i) * Dm + d0 + tx] = l;
    }
}

// ------------------------- bin smoothing + aggregate (float4) -------------------------
__global__ void __launch_bounds__(256)
smooth_k4(const float* __restrict__ raw, const float* __restrict__ sm,
          const float* __restrict__ agg, float* __restrict__ cm_out,
          float* __restrict__ cm1)
{
    const int tot4 = Bsz * Lsz * Lsz / 4;
    int idx = blockIdx.x * blockDim.x + threadIdx.x;
    if (idx >= tot4) return;
    const int PS = Lsz * Lsz / 4;
    int b   = idx / PS;
    int rem = idx % PS;

    const float4* base = reinterpret_cast<const float4*>(raw)
                       + (size_t)b * NBINS * PS + rem;
    float4 rv[NBINS];
    #pragma unroll
    for (int n = 0; n < NBINS; n++) rv[n] = base[(size_t)n * PS];

    float sw[5];
    #pragma unroll
    for (int k = 0; k < 5; k++) sw[k] = sm[k];

    float4* outb = reinterpret_cast<float4*>(cm_out) + (size_t)b * NBINS * PS + rem;
    float4 acc = make_float4(0.f, 0.f, 0.f, 0.f);
    #pragma unroll
    for (int n = 0; n < NBINS; n++) {
        float4 v = make_float4(0.f, 0.f, 0.f, 0.f);
        #pragma unroll
        for (int k = 0; k < 5; k++) {
            int m = n + k - 2;
            if (m >= 0 && m < NBINS) {
                v.x += sw[k] * rv[m].x;
                v.y += sw[k] * rv[m].y;
                v.z += sw[k] * rv[m].z;
                v.w += sw[k] * rv[m].w;
            }
        }
        outb[(size_t)n * PS] = v;
        float a = agg[n];
        acc.x += a * v.x; acc.y += a * v.y;
        acc.z += a * v.z; acc.w += a * v.w;
    }
    float4 o = make_float4(tanhf(acc.x), tanhf(acc.y), tanhf(acc.z), tanhf(acc.w));
    reinterpret_cast<float4*>(cm1)[idx] = o;
}

// ------------------------- integral image + head -------------------------
__global__ void colsum_k(const float* __restrict__ cm1, float* __restrict__ cs)
{
    int t = blockIdx.x * blockDim.x + threadIdx.x;
    if (t >= Bsz * Lsz) return;
    int b = t / Lsz, j = t % Lsz;
    const float* src = cm1 + (long long)b * Lsz * Lsz + j;
    float* dst       = cs  + (long long)b * Lsz * Lsz + j;
    float acc = 0.f;
    for (int i = 0; i < Lsz; i++) {
        acc += src[(long long)i * Lsz];
        dst[(long long)i * Lsz] = acc;
    }
}
__global__ void rowsum_k(const float* __restrict__ cs, float* __restrict__ I)
{
    int t = blockIdx.x * blockDim.x + threadIdx.x;
    if (t >= Bsz * Lsz) return;
    int b = t / Lsz, i = t % Lsz;
    const float* src = cs + (long long)b * Lsz * Lsz + (long long)i * Lsz;
    float* row = I + (long long)b * ISZ * ISZ + (long long)(i + 1) * ISZ;
    float acc = 0.f;
    row[0] = 0.f;
    for (int j = 0; j < Lsz; j++) { acc += src[j]; row[j + 1] = acc; }
    if (i == 0) {
        float* r0 = I + (long long)b * ISZ * ISZ;
        for (int c = 0; c < ISZ; c++) r0[c] = 0.f;
    }
}
__global__ void finalize_k(const float* __restrict__ I, const float* __restrict__ Lmat,
                           const float* __restrict__ biasp, float* __restrict__ pp)
{
    int b = blockIdx.x;
    __shared__ float terms[128];
    int t = threadIdx.x;
    float val = 0.f;
    if (t < PWc * PWc) {
        int p = t / PWc, q = t % PWc;
        const float* Ib = I + (long long)b * ISZ * ISZ;
        const int Hp = Lsz - PWc + 1;
        float w = Ib[(Hp + p) * ISZ + (Hp + q)] - Ib[(Hp + p) * ISZ + q]
                - Ib[p * ISZ + (Hp + q)]       + Ib[p * ISZ + q];
        val = tanhf(w) * Lmat[t];
    }
    terms[t] = val;
    __syncthreads();
    if (t == 0) {
        float s = 0.f;
        for (int i = 0; i < PWc * PWc; i++) s += terms[i];
        pp[b] = 1.0f / (1.0f + expf(-(s + biasp[0])));
    }
}

// ------------------------- host-side -------------------------
static int SMEM_TOTAL_BYTES(int BN) { return 2 * (2*128 + 2*BN) * (32*2 + 16); }
static int FA_SMEM() {
    return 2*128*144 + 2*(2*128*144) + 2*(2*64*272) + (256 + 256 + 128*64)*4;
}

static void gemm(int BN, const bf16* Ah, const bf16* Al, const bf16* Bh, const bf16* Bl,
                 float* C, bf16* Ch, bf16* Cl,
                 int M, int N, int K, int lda, int ldb, int ldc,
                 long long sA1, long long sA2, long long sB1, long long sB2,
                 long long sC1, long long sC2, int batch1, int batch2,
                 const float* bias, int biasMode, float alpha, int act,
                 const float* Cres, int outMode)
{
    dim3 grid(N / BN, M / 128, batch1 * batch2);
    if (BN == 128)
        gemm_mma<128><<<grid, 256, SMEM_TOTAL_BYTES(128)>>>(Ah, Al, Bh, Bl, C, Ch, Cl,
            K, lda, ldb, ldc, sA1, sA2, sB1, sB2, sC1, sC2, batch2,
            bias, biasMode, alpha, act, Cres, outMode);
    else
        gemm_mma<64><<<grid, 256, SMEM_TOTAL_BYTES(64)>>>(Ah, Al, Bh, Bl, C, Ch, Cl,
            K, lda, ldb, ldc, sA1, sA2, sB1, sB2, sC1, sC2, batch2,
            bias, biasMode, alpha, act, Cres, outMode);
}

struct Ptrs {
    float *xf, *cmraw, *cm1, *cs, *I;
    bf16 *xih,*xil,*wph,*wpl,*miwh,*miwl,*mowh,*mowl,*ciwh,*ciwl,*cowh,*cowl;
    bf16 *xh,*xl,*th,*tl,*qkh,*qkl,*vth,*vtl,*oh,*ol;
    bf16 *wbth,*wbtl,*hh,*hl;
};

static void run_mha(const Ptrs& P,
                    const bf16* qsh, const bf16* qsl,
                    const bf16* kvh, const bf16* kvl,
                    const bf16* iwh, const bf16* iwl, const float* in_b,
                    const bf16* owh, const bf16* owl, const float* out_b,
                    float* target, bool swapKV)
{
    const long long MD = (long long)Mrows * Dm;
    if (!swapKV) {
        gemm(128, qsh, qsl, iwh, iwl, nullptr, P.qkh, P.qkl,
             M2, 2*Dm, Dm, Dm, Dm, 2*Dm, 0,0,0,0,0,0, 1,1, in_b, 1, 1.f, 0, nullptr, 2);
        gemm(128, iwh + 2*Dm*Dm, iwl + 2*Dm*Dm, kvh, kvl, nullptr, P.vth, P.vtl,
             Dm, M2, Dm, Dm, Dm, M2, 0,0,0,0,0,0, 1,1, in_b + 2*Dm, 2, 1.f, 0, nullptr, 2);
    } else {
        gemm(128, qsh, qsl, iwh, iwl, nullptr, P.qkh, P.qkl,
             M2, Dm, Dm, Dm, Dm, 2*Dm, 0,0,0,0,0,0, 1,1, in_b, 1, 1.f, 0, nullptr, 2);
        gemm(128, kvh, kvl, iwh + Dm*Dm, iwl + Dm*Dm, nullptr,
             P.qkh + Dm + (long long)Mrows*2*Dm, P.qkl + Dm + (long long)Mrows*2*Dm,
             Mrows, Dm, Dm, Dm, Dm, 2*Dm,
             MD, 0, 0, 0, -(long long)Mrows*2*Dm, 0, 2, 1, in_b + Dm, 1, 1.f, 0, nullptr, 2);
        gemm(128, iwh + 2*Dm*Dm, iwl + 2*Dm*Dm, kvh, kvl, nullptr, P.vth + Mrows, P.vtl + Mrows,
             Dm, Mrows, Dm, Dm, Dm, M2,
             0, 0, MD, 0, -(long long)Mrows, 0, 2, 1, in_b + 2*Dm, 2, 1.f, 0, nullptr, 2);
    }
    fused_attn<<<dim3(4, 2*Bsz*Hh), 256, FA_SMEM()>>>(
        P.qkh, P.qkl, P.vth, P.vtl, P.oh, P.ol);
    gemm(128, P.oh, P.ol, owh, owl, target, nullptr, nullptr,
         M2, Dm, Dm, Dm, Dm, Dm, 0,0,0,0,0,0, 1,1, out_b, 1, 1.f, 0, target, 1);
}

extern "C" void kernel_launch(void* const* d_in, const int* in_sizes, int n_in,
                              void* d_out, int out_size)
{
    const float* x1i     = (const float*)d_in[0];
    const float* x2i     = (const float*)d_in[1];
    const float* proj_w  = (const float*)d_in[2];
    const float* proj_b  = (const float*)d_in[3];
    const float* mha_in_w  = (const float*)d_in[4];
    const float* mha_in_b  = (const float*)d_in[5];
    const float* mha_out_w = (const float*)d_in[6];
    const float* mha_out_b = (const float*)d_in[7];
    const float* ca_in_w   = (const float*)d_in[8];
    const float* ca_in_b   = (const float*)d_in[9];
    const float* ca_out_w  = (const float*)d_in[10];
    const float* ca_out_b  = (const float*)d_in[11];
    const float* Wbins   = (const float*)d_in[12];
    const float* agg     = (const float*)d_in[13];
    const float* Lmat    = (const float*)d_in[14];
    const float* biasp   = (const float*)d_in[15];
    const float* smooth  = (const float*)d_in[16];

    cudaFuncSetAttribute(gemm_mma<128>, cudaFuncAttributeMaxDynamicSharedMemorySize,
                         SMEM_TOTAL_BYTES(128));
    cudaFuncSetAttribute(gemm_mma<64>,  cudaFuncAttributeMaxDynamicSharedMemorySize,
                         SMEM_TOTAL_BYTES(64));
    cudaFuncSetAttribute(fused_attn, cudaFuncAttributeMaxDynamicSharedMemorySize,
                         FA_SMEM());

    Ptrs P;
    cudaGetSymbolAddress((void**)&P.xf, g_xf);
    cudaGetSymbolAddress((void**)&P.cmraw, g_cmraw);
    cudaGetSymbolAddress((void**)&P.cm1, g_cm1);   cudaGetSymbolAddress((void**)&P.cs, g_cs);
    cudaGetSymbolAddress((void**)&P.I, g_I);
    cudaGetSymbolAddress((void**)&P.xih, g_xih);   cudaGetSymbolAddress((void**)&P.xil, g_xil);
    cudaGetSymbolAddress((void**)&P.wph, g_wph);   cudaGetSymbolAddress((void**)&P.wpl, g_wpl);
    cudaGetSymbolAddress((void**)&P.miwh, g_miwh); cudaGetSymbolAddress((void**)&P.miwl, g_miwl);
    cudaGetSymbolAddress((void**)&P.mowh, g_mowh); cudaGetSymbolAddress((void**)&P.mowl, g_mowl);
    cudaGetSymbolAddress((void**)&P.ciwh, g_ciwh); cudaGetSymbolAddress((void**)&P.ciwl, g_ciwl);
    cudaGetSymbolAddress((void**)&P.cowh, g_cowh); cudaGetSymbolAddress((void**)&P.cowl, g_cowl);
    cudaGetSymbolAddress((void**)&P.xh, g_xh);     cudaGetSymbolAddress((void**)&P.xl, g_xl);
    cudaGetSymbolAddress((void**)&P.th, g_th);     cudaGetSymbolAddress((void**)&P.tl, g_tl);
    cudaGetSymbolAddress((void**)&P.qkh, g_qkh);   cudaGetSymbolAddress((void**)&P.qkl, g_qkl);
    cudaGetSymbolAddress((void**)&P.vth, g_vth);   cudaGetSymbolAddress((void**)&P.vtl, g_vtl);
    cudaGetSymbolAddress((void**)&P.oh, g_oh);     cudaGetSymbolAddress((void**)&P.ol, g_ol);
    cudaGetSymbolAddress((void**)&P.wbth, g_wbth); cudaGetSymbolAddress((void**)&P.wbtl, g_wbtl);
    cudaGetSymbolAddress((void**)&P.hh, g_hh);     cudaGetSymbolAddress((void**)&P.hl, g_hl);

    float* out = (float*)d_out;
    float* pp_out = out + (out_size - Bsz);

    const long long MD  = (long long)Mrows * Dm;
    const long long MID = (long long)Mrows * IDIM;
    const int NXD2 = M2 * Dm;

    // 0. one-shot splits: x1 -> xih[0:], x2 -> xih[MID:], weights
    split_all<<<(CUM7 + 255)/256, 256>>>(
        x1i, x2i, proj_w, mha_in_w, mha_out_w, ca_in_w, ca_out_w,
        P.xih, P.xil, P.xih + MID, P.xil + MID, P.wph, P.wpl,
        P.miwh, P.miwl, P.mowh, P.mowl, P.ciwh, P.ciwl, P.cowh, P.cowl);
    {
        dim3 g(HALFc/32, Dm/32, NBINS);
        transpose_split_k<<<g, dim3(32,8)>>>(Wbins, P.wbth, P.wbtl);
    }

    // 1. input projection: single M=8192 launch (256 CTAs = 1 wave @ 2 CTA/SM)
    gemm(128, P.xih, P.xil, P.wph, P.wpl, P.xf, P.xh, P.xl,
         M2, Dm, IDIM, IDIM, IDIM, Dm, 0,0,0,0,0,0, 1,1, proj_b, 1, 1.f, 0, nullptr, 3);

    // 2. self-attention (+residual)
    run_mha(P, P.xh, P.xl, P.xh, P.xl, P.miwh, P.miwl, mha_in_b,
            P.mowh, P.mowl, mha_out_b, P.xf, false);

    // 3. tanh -> planes
    tanh_split_k<<<(NXD2/4 + 255)/256, 256>>>(P.xf, P.th, P.tl, NXD2/4);

    // 4. cross-attention (+residual), swapped KV
    run_mha(P, P.th, P.tl, P.th, P.tl, P.ciwh, P.ciwl, ca_in_b,
            P.cowh, P.cowl, ca_out_b, P.xf, true);

    // 5. tanh -> planes
    tanh_split_k<<<(NXD2/4 + 255)/256, 256>>>(P.xf, P.th, P.tl, NXD2/4);

    // 6. h = tanh(x @ Wbins)
    gemm(128, P.th, P.tl, P.wbth, P.wbtl, nullptr, P.hh, P.hl,
         Lsz, HALFc, Dm, Dm, Dm, HALFc,
         (long long)Lsz*Dm, 0, 0, (long long)HALFc*Dm,
         (long long)NBINS*Lsz*HALFc, (long long)Lsz*HALFc, 2*Bsz, NBINS,
         nullptr, 0, 1.f, 1, nullptr, 2);

    // 7. cm_raw = h1 h2^T (batch 200)
    {
        const long long hhalf = (long long)Bsz*NBINS*Lsz*HALFc;
        gemm(128, P.hh, P.hl, P.hh + hhalf, P.hl + hhalf, P.cmraw, nullptr, nullptr,
             Lsz, Lsz, HALFc, HALFc, HALFc, Lsz,
             (long long)Lsz*HALFc, 0, (long long)Lsz*HALFc, 0,
             (long long)Lsz*Lsz, 0, Bsz*NBINS, 1,
             nullptr, 0, 1.f, 0, nullptr, 1);
    }

    // 8. smoothing -> cm + cm1
    {
        int tot4 = Bsz * Lsz * Lsz / 4;
        smooth_k4<<<(tot4 + 255) / 256, 256>>>(P.cmraw, smooth, agg, out, P.cm1);
    }

    // 9. integral image
    colsum_k<<<(Bsz*Lsz + 255) / 256, 256>>>(P.cm1, P.cs);
    rowsum_k<<<(Bsz*Lsz + 255) / 256, 256>>>(P.cs, P.I);

    // 10. head
    finalize_k<<<Bsz, 128>>>(P.I, Lmat, biasp, pp_out);
}